// round 1
// baseline (speedup 1.0000x reference)
#include <cuda_runtime.h>
#include <math.h>

#define BATCH 32
#define TOK 197
#define ROWS (BATCH*TOK)      // 6304
#define DIM 768
#define HEADS 12
#define DHD 64
#define FFD 3072
#define QKVD 2304
#define NPATCH 196
#define NCLSD 1000

// ---------------- scratch (static device allocations; no cudaMalloc) ----------------
__device__ float g_x   [ROWS*DIM];                  // residual stream
__device__ float g_h   [ROWS*DIM];                  // LN output
__device__ float g_qkv [ROWS*QKVD];
__device__ float g_q   [BATCH*HEADS*TOK*DHD];
__device__ float g_kk  [BATCH*HEADS*TOK*DHD];
__device__ float g_v   [BATCH*HEADS*TOK*DHD];
__device__ float g_attn[ROWS*DIM];                  // attn out / patch tokens
__device__ float g_ff  [ROWS*FFD];                  // MLP intermediate / im2col patches / head hidden

// ---------------- SGEMM: C[M,N] = act(A[M,K] @ W[N,K]^T + bias) + res ----------------
// BM=128, BN=64, BK=16, 256 threads, 8x4 micro-tile per thread.
__global__ __launch_bounds__(256) void sgemm(
    const float* __restrict__ A, int lda,
    const float* __restrict__ W,          // [N, K] row-major
    const float* __restrict__ bias,       // [N] or null
    const float* __restrict__ res,        // [M, ldc] or null (added after activation)
    float* __restrict__ C, int ldc,
    int M, int N, int K, int act)         // act: 0=none, 1=gelu(exact), 2=tanh
{
    __shared__ float As[16][128];
    __shared__ float Bs[16][64];
    int tid = threadIdx.x;
    int tx = tid & 15, ty = tid >> 4;
    int row0 = blockIdx.y * 128;
    int col0 = blockIdx.x * 64;

    float acc[8][4];
#pragma unroll
    for (int i = 0; i < 8; i++)
#pragma unroll
        for (int j = 0; j < 4; j++) acc[i][j] = 0.f;

    for (int k0 = 0; k0 < K; k0 += 16) {
        // load A tile (128x16) as float4, store transposed As[k][m]
#pragma unroll
        for (int i = 0; i < 2; i++) {
            int idx = tid + i * 256;
            int r = idx >> 2;
            int c = (idx & 3) << 2;
            int gr = row0 + r;
            float4 v = make_float4(0.f, 0.f, 0.f, 0.f);
            if (gr < M) v = *(const float4*)(A + (size_t)gr * lda + k0 + c);
            As[c + 0][r] = v.x; As[c + 1][r] = v.y; As[c + 2][r] = v.z; As[c + 3][r] = v.w;
        }
        // load W tile (64 rows x 16 k) as float4, store Bs[k][n]
        {
            int n = tid >> 2;
            int c = (tid & 3) << 2;
            int gn = col0 + n;
            float4 v = make_float4(0.f, 0.f, 0.f, 0.f);
            if (gn < N) v = *(const float4*)(W + (size_t)gn * K + k0 + c);
            Bs[c + 0][n] = v.x; Bs[c + 1][n] = v.y; Bs[c + 2][n] = v.z; Bs[c + 3][n] = v.w;
        }
        __syncthreads();
#pragma unroll
        for (int kk = 0; kk < 16; kk++) {
            float4 a0 = *(const float4*)&As[kk][ty * 8];
            float4 a1 = *(const float4*)&As[kk][ty * 8 + 4];
            float4 b  = *(const float4*)&Bs[kk][tx * 4];
            float av[8] = {a0.x, a0.y, a0.z, a0.w, a1.x, a1.y, a1.z, a1.w};
            float bv[4] = {b.x, b.y, b.z, b.w};
#pragma unroll
            for (int i = 0; i < 8; i++)
#pragma unroll
                for (int j = 0; j < 4; j++)
                    acc[i][j] += av[i] * bv[j];
        }
        __syncthreads();
    }

#pragma unroll
    for (int i = 0; i < 8; i++) {
        int gr = row0 + ty * 8 + i;
        if (gr >= M) continue;
#pragma unroll
        for (int j = 0; j < 4; j++) {
            int gn = col0 + tx * 4 + j;
            if (gn >= N) continue;
            float v = acc[i][j];
            if (bias) v += bias[gn];
            if (act == 1)      v = 0.5f * v * (1.0f + erff(v * 0.70710678118654752f));
            else if (act == 2) v = tanhf(v);
            if (res) v += res[(size_t)gr * ldc + gn];
            C[(size_t)gr * ldc + gn] = v;
        }
    }
}

// ---------------- LayerNorm: one block per row (row length 768) ----------------
__global__ __launch_bounds__(256) void ln_kernel(
    const float* __restrict__ x, const float* __restrict__ w,
    const float* __restrict__ b, float* __restrict__ y)
{
    int row = blockIdx.x;
    const float* xr = x + (size_t)row * DIM;
    __shared__ float red[256];
    int tid = threadIdx.x;

    float s = 0.f;
    for (int i = tid; i < DIM; i += 256) s += xr[i];
    red[tid] = s; __syncthreads();
    for (int o = 128; o > 0; o >>= 1) { if (tid < o) red[tid] += red[tid + o]; __syncthreads(); }
    float mean = red[0] * (1.0f / DIM);
    __syncthreads();

    float s2 = 0.f;
    for (int i = tid; i < DIM; i += 256) { float d = xr[i] - mean; s2 += d * d; }
    red[tid] = s2; __syncthreads();
    for (int o = 128; o > 0; o >>= 1) { if (tid < o) red[tid] += red[tid + o]; __syncthreads(); }
    float inv = rsqrtf(red[0] * (1.0f / DIM) + 1e-5f);

    float* yr = y + (size_t)row * DIM;
    for (int i = tid; i < DIM; i += 256)
        yr[i] = (xr[i] - mean) * inv * w[i] + b[i];
}

// ---------------- im2col: (B,C,224,224) -> patches [B*196, 768] (pr,pc,c order) -------
__global__ void im2col_kernel(const float* __restrict__ img, float* __restrict__ patches)
{
    int idx = blockIdx.x * blockDim.x + threadIdx.x;
    if (idx >= BATCH * NPATCH * DIM) return;
    int e = idx % DIM;
    int m = idx / DIM;
    int b = m / NPATCH, p = m % NPATCH;
    int gr = p / 14, gc = p % 14;
    int c = e % 3;
    int pp = e / 3;
    int pr = pp / 16, pc = pp % 16;
    patches[idx] = img[(((size_t)b * 3 + c) * 224 + gr * 16 + pr) * 224 + gc * 16 + pc];
}

// ---------------- assemble: cls + tokens + pos_emb -> x [B,197,768] ----------------
__global__ void assemble_kernel(const float* __restrict__ tokens,
                                const float* __restrict__ cls,
                                const float* __restrict__ pos,
                                float* __restrict__ x)
{
    int idx = blockIdx.x * blockDim.x + threadIdx.x;
    if (idx >= ROWS * DIM) return;
    int d = idx % DIM;
    int r = idx / DIM;
    int b = r / TOK, n = r % TOK;
    float v = (n == 0) ? cls[d] : tokens[((size_t)b * NPATCH + (n - 1)) * DIM + d];
    x[idx] = v + pos[(size_t)n * DIM + d];
}

// ---------------- qkv reorder: [b,n, h*192+d*3+s] -> Q/K/V [(b*H+h)*N+n, d] ----------
__global__ void reorder_qkv(const float* __restrict__ qkv,
                            float* __restrict__ Q, float* __restrict__ K, float* __restrict__ V)
{
    int idx = blockIdx.x * blockDim.x + threadIdx.x;
    const int total = BATCH * HEADS * TOK * DHD;
    if (idx >= total) return;
    int d = idx & 63;
    int n = (idx >> 6) % TOK;
    int h = (idx >> 6) / TOK % HEADS;
    int b = idx / (64 * TOK * HEADS);
    const float* src = qkv + ((size_t)(b * TOK + n)) * QKVD + h * 192 + d * 3;
    Q[idx] = src[0];
    K[idx] = src[1];
    V[idx] = src[2];
}

// ---------------- attention: one block per (b,h); K,V resident in smem ----------------
// dyn smem: ks[197*65] + vs[197*65]
__global__ __launch_bounds__(256) void attn_kernel(
    const float* __restrict__ Q, const float* __restrict__ K,
    const float* __restrict__ V, float* __restrict__ out)
{
    extern __shared__ float sm[];
    float* ks = sm;
    float* vs = sm + TOK * 65;
    __shared__ float qs[DHD];
    __shared__ float sc[TOK];
    __shared__ float red[256];

    int bh = blockIdx.x;
    int b = bh / HEADS, h = bh % HEADS;
    int tid = threadIdx.x;
    const float* Qb = Q + (size_t)bh * TOK * DHD;
    const float* Kb = K + (size_t)bh * TOK * DHD;
    const float* Vb = V + (size_t)bh * TOK * DHD;

    for (int i = tid; i < TOK * DHD; i += 256) {
        int n = i >> 6, d = i & 63;
        ks[n * 65 + d] = Kb[i];
        vs[n * 65 + d] = Vb[i];
    }
    __syncthreads();

    for (int nq = 0; nq < TOK; nq++) {
        if (tid < DHD) qs[tid] = Qb[(size_t)nq * DHD + tid];
        __syncthreads();
        if (tid < TOK) {
            const float* kr = &ks[tid * 65];
            float s = 0.f;
#pragma unroll
            for (int d = 0; d < DHD; d++) s += kr[d] * qs[d];
            sc[tid] = s * 0.125f;
        }
        __syncthreads();
        // max reduce
        red[tid] = (tid < TOK) ? sc[tid] : -1e30f;
        __syncthreads();
        for (int o = 128; o > 0; o >>= 1) { if (tid < o) red[tid] = fmaxf(red[tid], red[tid + o]); __syncthreads(); }
        float mx = red[0];
        __syncthreads();
        float p = (tid < TOK) ? expf(sc[tid] - mx) : 0.f;
        if (tid < TOK) sc[tid] = p;
        red[tid] = p;
        __syncthreads();
        for (int o = 128; o > 0; o >>= 1) { if (tid < o) red[tid] += red[tid + o]; __syncthreads(); }
        float inv = 1.0f / red[0];
        __syncthreads();
        // out = softmax @ V ; 4 key-groups x 64 dims
        int g = tid >> 6, d = tid & 63;
        float acc = 0.f;
        for (int kk = g; kk < TOK; kk += 4) acc += sc[kk] * vs[kk * 65 + d];
        red[tid] = acc;
        __syncthreads();
        if (tid < DHD) {
            float o = (red[tid] + red[tid + 64] + red[tid + 128] + red[tid + 192]) * inv;
            out[((size_t)(b * TOK + nq)) * DIM + h * DHD + tid] = o;
        }
        __syncthreads();
    }
}

// ---------------- host ----------------
static void launch_gemm(const float* A, int lda, const float* W, const float* bias,
                        const float* res, float* C, int ldc,
                        int M, int N, int K, int act)
{
    dim3 grid((N + 63) / 64, (M + 127) / 128);
    sgemm<<<grid, 256>>>(A, lda, W, bias, res, C, ldc, M, N, K, act);
}

extern "C" void kernel_launch(void* const* d_in, const int* in_sizes, int n_in,
                              void* d_out, int out_size)
{
    const float* img      = (const float*)d_in[0];
    const float* patch_w  = (const float*)d_in[1];
    const float* patch_b  = (const float*)d_in[2];
    const float* cls_tok  = (const float*)d_in[3];
    const float* pos_emb  = (const float*)d_in[4];
    const float* ln1_w    = (const float*)d_in[5];
    const float* ln1_b    = (const float*)d_in[6];
    const float* qkv_w    = (const float*)d_in[7];
    const float* qkv_b    = (const float*)d_in[8];
    const float* proj_w   = (const float*)d_in[9];
    const float* proj_b   = (const float*)d_in[10];
    const float* ln2_w    = (const float*)d_in[11];
    const float* ln2_b    = (const float*)d_in[12];
    const float* ff1_w    = (const float*)d_in[13];
    const float* ff1_b    = (const float*)d_in[14];
    const float* ff2_w    = (const float*)d_in[15];
    const float* ff2_b    = (const float*)d_in[16];
    const float* head1_w  = (const float*)d_in[17];
    const float* head1_b  = (const float*)d_in[18];
    const float* head2_w  = (const float*)d_in[19];
    const float* head2_b  = (const float*)d_in[20];
    float* out = (float*)d_out;

    float *x, *h, *qkv, *q, *k, *v, *attn, *ff;
    cudaGetSymbolAddress((void**)&x,    g_x);
    cudaGetSymbolAddress((void**)&h,    g_h);
    cudaGetSymbolAddress((void**)&qkv,  g_qkv);
    cudaGetSymbolAddress((void**)&q,    g_q);
    cudaGetSymbolAddress((void**)&k,    g_kk);
    cudaGetSymbolAddress((void**)&v,    g_v);
    cudaGetSymbolAddress((void**)&attn, g_attn);
    cudaGetSymbolAddress((void**)&ff,   g_ff);

    const int ATTN_SMEM = 2 * TOK * 65 * (int)sizeof(float);
    cudaFuncSetAttribute(attn_kernel, cudaFuncAttributeMaxDynamicSharedMemorySize, ATTN_SMEM);

    // patch embed: im2col -> GEMM -> assemble with cls + pos
    {
        int tot = BATCH * NPATCH * DIM;
        im2col_kernel<<<(tot + 255) / 256, 256>>>(img, ff);
        launch_gemm(ff, DIM, patch_w, patch_b, nullptr, attn, DIM,
                    BATCH * NPATCH, DIM, DIM, 0);
        int tot2 = ROWS * DIM;
        assemble_kernel<<<(tot2 + 255) / 256, 256>>>(attn, cls_tok, pos_emb, x);
    }

    const int NELEM = BATCH * HEADS * TOK * DHD;
    for (int l = 0; l < 12; l++) {
        // --- attention sub-block ---
        ln_kernel<<<ROWS, 256>>>(x, ln1_w + (size_t)l * DIM, ln1_b + (size_t)l * DIM, h);
        launch_gemm(h, DIM, qkv_w + (size_t)l * QKVD * DIM, qkv_b + (size_t)l * QKVD,
                    nullptr, qkv, QKVD, ROWS, QKVD, DIM, 0);
        reorder_qkv<<<(NELEM + 255) / 256, 256>>>(qkv, q, k, v);
        attn_kernel<<<BATCH * HEADS, 256, ATTN_SMEM>>>(q, k, v, attn);
        launch_gemm(attn, DIM, proj_w + (size_t)l * DIM * DIM, proj_b + (size_t)l * DIM,
                    x, x, DIM, ROWS, DIM, DIM, 0);
        // --- MLP sub-block ---
        ln_kernel<<<ROWS, 256>>>(x, ln2_w + (size_t)l * DIM, ln2_b + (size_t)l * DIM, h);
        launch_gemm(h, DIM, ff1_w + (size_t)l * FFD * DIM, ff1_b + (size_t)l * FFD,
                    nullptr, ff, FFD, ROWS, FFD, DIM, 1 /*gelu*/);
        launch_gemm(ff, FFD, ff2_w + (size_t)l * DIM * FFD, ff2_b + (size_t)l * DIM,
                    x, x, DIM, ROWS, DIM, FFD, 0);
    }

    // head: latent = x[:, 0, :]  (row stride TOK*DIM)
    launch_gemm(x, TOK * DIM, head1_w, head1_b, nullptr, ff, FFD,
                BATCH, FFD, DIM, 2 /*tanh*/);
    launch_gemm(ff, FFD, head2_w, head2_b, nullptr, out, NCLSD,
                BATCH, NCLSD, FFD, 0);
}

// round 2
// speedup vs baseline: 1.0010x; 1.0010x over previous
#include <cuda_runtime.h>
#include <math.h>

#define BATCH 32
#define TOK 197
#define ROWS (BATCH*TOK)      // 6304
#define DIM 768
#define HEADS 12
#define DHD 64
#define FFD 3072
#define QKVD 2304
#define NPATCH 196
#define NCLSD 1000

// ---------------- scratch (static device allocations; no cudaMalloc) ----------------
__device__ float g_x   [ROWS*DIM];                  // residual stream
__device__ float g_h   [ROWS*DIM];                  // LN output
__device__ float g_qkv [ROWS*QKVD];
__device__ float g_q   [BATCH*HEADS*TOK*DHD];
__device__ float g_kk  [BATCH*HEADS*TOK*DHD];
__device__ float g_v   [BATCH*HEADS*TOK*DHD];
__device__ float g_attn[ROWS*DIM];                  // attn out / patch tokens
__device__ float g_ff  [ROWS*FFD];                  // MLP intermediate / im2col patches / head hidden

// ---------------- SGEMM: C[M,N] = act(A[M,K] @ W[N,K]^T + bias) + res ----------------
// BM=128, BN=64, BK=16, 256 threads, 8x4 micro-tile per thread.
__global__ __launch_bounds__(256) void sgemm(
    const float* __restrict__ A, int lda,
    const float* __restrict__ W,          // [N, K] row-major
    const float* __restrict__ bias,       // [N] or null
    const float* __restrict__ res,        // [M, ldc] or null (added after activation)
    float* __restrict__ C, int ldc,
    int M, int N, int K, int act)         // act: 0=none, 1=gelu(exact), 2=tanh
{
    __shared__ float As[16][128];
    __shared__ float Bs[16][64];
    int tid = threadIdx.x;
    int tx = tid & 15, ty = tid >> 4;
    int row0 = blockIdx.y * 128;
    int col0 = blockIdx.x * 64;

    float acc[8][4];
#pragma unroll
    for (int i = 0; i < 8; i++)
#pragma unroll
        for (int j = 0; j < 4; j++) acc[i][j] = 0.f;

    for (int k0 = 0; k0 < K; k0 += 16) {
        // load A tile (128x16) as float4, store transposed As[k][m]
#pragma unroll
        for (int i = 0; i < 2; i++) {
            int idx = tid + i * 256;
            int r = idx >> 2;
            int c = (idx & 3) << 2;
            int gr = row0 + r;
            float4 v = make_float4(0.f, 0.f, 0.f, 0.f);
            if (gr < M) v = *(const float4*)(A + (size_t)gr * lda + k0 + c);
            As[c + 0][r] = v.x; As[c + 1][r] = v.y; As[c + 2][r] = v.z; As[c + 3][r] = v.w;
        }
        // load W tile (64 rows x 16 k) as float4, store Bs[k][n]
        {
            int n = tid >> 2;
            int c = (tid & 3) << 2;
            int gn = col0 + n;
            float4 v = make_float4(0.f, 0.f, 0.f, 0.f);
            if (gn < N) v = *(const float4*)(W + (size_t)gn * K + k0 + c);
            Bs[c + 0][n] = v.x; Bs[c + 1][n] = v.y; Bs[c + 2][n] = v.z; Bs[c + 3][n] = v.w;
        }
        __syncthreads();
#pragma unroll
        for (int kk = 0; kk < 16; kk++) {
            float4 a0 = *(const float4*)&As[kk][ty * 8];
            float4 a1 = *(const float4*)&As[kk][ty * 8 + 4];
            float4 b  = *(const float4*)&Bs[kk][tx * 4];
            float av[8] = {a0.x, a0.y, a0.z, a0.w, a1.x, a1.y, a1.z, a1.w};
            float bv[4] = {b.x, b.y, b.z, b.w};
#pragma unroll
            for (int i = 0; i < 8; i++)
#pragma unroll
                for (int j = 0; j < 4; j++)
                    acc[i][j] += av[i] * bv[j];
        }
        __syncthreads();
    }

#pragma unroll
    for (int i = 0; i < 8; i++) {
        int gr = row0 + ty * 8 + i;
        if (gr >= M) continue;
#pragma unroll
        for (int j = 0; j < 4; j++) {
            int gn = col0 + tx * 4 + j;
            if (gn >= N) continue;
            float v = acc[i][j];
            if (bias) v += bias[gn];
            if (act == 1)      v = 0.5f * v * (1.0f + erff(v * 0.70710678118654752f));
            else if (act == 2) v = tanhf(v);
            if (res) v += res[(size_t)gr * ldc + gn];
            C[(size_t)gr * ldc + gn] = v;
        }
    }
}

// ---------------- LayerNorm: one block per row (row length 768) ----------------
__global__ __launch_bounds__(256) void ln_kernel(
    const float* __restrict__ x, const float* __restrict__ w,
    const float* __restrict__ b, float* __restrict__ y)
{
    int row = blockIdx.x;
    const float* xr = x + (size_t)row * DIM;
    __shared__ float red[256];
    int tid = threadIdx.x;

    float s = 0.f;
    for (int i = tid; i < DIM; i += 256) s += xr[i];
    red[tid] = s; __syncthreads();
    for (int o = 128; o > 0; o >>= 1) { if (tid < o) red[tid] += red[tid + o]; __syncthreads(); }
    float mean = red[0] * (1.0f / DIM);
    __syncthreads();

    float s2 = 0.f;
    for (int i = tid; i < DIM; i += 256) { float d = xr[i] - mean; s2 += d * d; }
    red[tid] = s2; __syncthreads();
    for (int o = 128; o > 0; o >>= 1) { if (tid < o) red[tid] += red[tid + o]; __syncthreads(); }
    float inv = rsqrtf(red[0] * (1.0f / DIM) + 1e-5f);

    float* yr = y + (size_t)row * DIM;
    for (int i = tid; i < DIM; i += 256)
        yr[i] = (xr[i] - mean) * inv * w[i] + b[i];
}

// ---------------- im2col: (B,C,224,224) -> patches [B*196, 768] (pr,pc,c order) -------
__global__ void im2col_kernel(const float* __restrict__ img, float* __restrict__ patches)
{
    int idx = blockIdx.x * blockDim.x + threadIdx.x;
    if (idx >= BATCH * NPATCH * DIM) return;
    int e = idx % DIM;
    int m = idx / DIM;
    int b = m / NPATCH, p = m % NPATCH;
    int gr = p / 14, gc = p % 14;
    int c = e % 3;
    int pp = e / 3;
    int pr = pp / 16, pc = pp % 16;
    patches[idx] = img[(((size_t)b * 3 + c) * 224 + gr * 16 + pr) * 224 + gc * 16 + pc];
}

// ---------------- assemble: cls + tokens + pos_emb -> x [B,197,768] ----------------
__global__ void assemble_kernel(const float* __restrict__ tokens,
                                const float* __restrict__ cls,
                                const float* __restrict__ pos,
                                float* __restrict__ x)
{
    int idx = blockIdx.x * blockDim.x + threadIdx.x;
    if (idx >= ROWS * DIM) return;
    int d = idx % DIM;
    int r = idx / DIM;
    int b = r / TOK, n = r % TOK;
    float v = (n == 0) ? cls[d] : tokens[((size_t)b * NPATCH + (n - 1)) * DIM + d];
    x[idx] = v + pos[(size_t)n * DIM + d];
}

// ---------------- qkv reorder: [b,n, h*192+d*3+s] -> Q/K/V [(b*H+h)*N+n, d] ----------
__global__ void reorder_qkv(const float* __restrict__ qkv,
                            float* __restrict__ Q, float* __restrict__ K, float* __restrict__ V)
{
    int idx = blockIdx.x * blockDim.x + threadIdx.x;
    const int total = BATCH * HEADS * TOK * DHD;
    if (idx >= total) return;
    int d = idx & 63;
    int n = (idx >> 6) % TOK;
    int h = (idx >> 6) / TOK % HEADS;
    int b = idx / (64 * TOK * HEADS);
    const float* src = qkv + ((size_t)(b * TOK + n)) * QKVD + h * 192 + d * 3;
    Q[idx] = src[0];
    K[idx] = src[1];
    V[idx] = src[2];
}

// ---------------- attention: one block per (b,h); K,V resident in smem ----------------
// dyn smem: ks[197*65] + vs[197*65]
__global__ __launch_bounds__(256) void attn_kernel(
    const float* __restrict__ Q, const float* __restrict__ K,
    const float* __restrict__ V, float* __restrict__ out)
{
    extern __shared__ float sm[];
    float* ks = sm;
    float* vs = sm + TOK * 65;
    __shared__ float qs[DHD];
    __shared__ float sc[TOK];
    __shared__ float red[256];

    int bh = blockIdx.x;
    int b = bh / HEADS, h = bh % HEADS;
    int tid = threadIdx.x;
    const float* Qb = Q + (size_t)bh * TOK * DHD;
    const float* Kb = K + (size_t)bh * TOK * DHD;
    const float* Vb = V + (size_t)bh * TOK * DHD;

    for (int i = tid; i < TOK * DHD; i += 256) {
        int n = i >> 6, d = i & 63;
        ks[n * 65 + d] = Kb[i];
        vs[n * 65 + d] = Vb[i];
    }
    __syncthreads();

    for (int nq = 0; nq < TOK; nq++) {
        if (tid < DHD) qs[tid] = Qb[(size_t)nq * DHD + tid];
        __syncthreads();
        if (tid < TOK) {
            const float* kr = &ks[tid * 65];
            float s = 0.f;
#pragma unroll
            for (int d = 0; d < DHD; d++) s += kr[d] * qs[d];
            sc[tid] = s * 0.125f;
        }
        __syncthreads();
        // max reduce
        red[tid] = (tid < TOK) ? sc[tid] : -1e30f;
        __syncthreads();
        for (int o = 128; o > 0; o >>= 1) { if (tid < o) red[tid] = fmaxf(red[tid], red[tid + o]); __syncthreads(); }
        float mx = red[0];
        __syncthreads();
        float p = (tid < TOK) ? expf(sc[tid] - mx) : 0.f;
        if (tid < TOK) sc[tid] = p;
        red[tid] = p;
        __syncthreads();
        for (int o = 128; o > 0; o >>= 1) { if (tid < o) red[tid] += red[tid + o]; __syncthreads(); }
        float inv = 1.0f / red[0];
        __syncthreads();
        // out = softmax @ V ; 4 key-groups x 64 dims
        int g = tid >> 6, d = tid & 63;
        float acc = 0.f;
        for (int kk = g; kk < TOK; kk += 4) acc += sc[kk] * vs[kk * 65 + d];
        red[tid] = acc;
        __syncthreads();
        if (tid < DHD) {
            float o = (red[tid] + red[tid + 64] + red[tid + 128] + red[tid + 192]) * inv;
            out[((size_t)(b * TOK + nq)) * DIM + h * DHD + tid] = o;
        }
        __syncthreads();
    }
}

// ---------------- host ----------------
static void launch_gemm(const float* A, int lda, const float* W, const float* bias,
                        const float* res, float* C, int ldc,
                        int M, int N, int K, int act)
{
    dim3 grid((N + 63) / 64, (M + 127) / 128);
    sgemm<<<grid, 256>>>(A, lda, W, bias, res, C, ldc, M, N, K, act);
}

extern "C" void kernel_launch(void* const* d_in, const int* in_sizes, int n_in,
                              void* d_out, int out_size)
{
    const float* img      = (const float*)d_in[0];
    const float* patch_w  = (const float*)d_in[1];
    const float* patch_b  = (const float*)d_in[2];
    const float* cls_tok  = (const float*)d_in[3];
    const float* pos_emb  = (const float*)d_in[4];
    const float* ln1_w    = (const float*)d_in[5];
    const float* ln1_b    = (const float*)d_in[6];
    const float* qkv_w    = (const float*)d_in[7];
    const float* qkv_b    = (const float*)d_in[8];
    const float* proj_w   = (const float*)d_in[9];
    const float* proj_b   = (const float*)d_in[10];
    const float* ln2_w    = (const float*)d_in[11];
    const float* ln2_b    = (const float*)d_in[12];
    const float* ff1_w    = (const float*)d_in[13];
    const float* ff1_b    = (const float*)d_in[14];
    const float* ff2_w    = (const float*)d_in[15];
    const float* ff2_b    = (const float*)d_in[16];
    const float* head1_w  = (const float*)d_in[17];
    const float* head1_b  = (const float*)d_in[18];
    const float* head2_w  = (const float*)d_in[19];
    const float* head2_b  = (const float*)d_in[20];
    float* out = (float*)d_out;

    float *x, *h, *qkv, *q, *k, *v, *attn, *ff;
    cudaGetSymbolAddress((void**)&x,    g_x);
    cudaGetSymbolAddress((void**)&h,    g_h);
    cudaGetSymbolAddress((void**)&qkv,  g_qkv);
    cudaGetSymbolAddress((void**)&q,    g_q);
    cudaGetSymbolAddress((void**)&k,    g_kk);
    cudaGetSymbolAddress((void**)&v,    g_v);
    cudaGetSymbolAddress((void**)&attn, g_attn);
    cudaGetSymbolAddress((void**)&ff,   g_ff);

    const int ATTN_SMEM = 2 * TOK * 65 * (int)sizeof(float);
    cudaFuncSetAttribute(attn_kernel, cudaFuncAttributeMaxDynamicSharedMemorySize, ATTN_SMEM);

    // patch embed: im2col -> GEMM -> assemble with cls + pos
    {
        int tot = BATCH * NPATCH * DIM;
        im2col_kernel<<<(tot + 255) / 256, 256>>>(img, ff);
        launch_gemm(ff, DIM, patch_w, patch_b, nullptr, attn, DIM,
                    BATCH * NPATCH, DIM, DIM, 0);
        int tot2 = ROWS * DIM;
        assemble_kernel<<<(tot2 + 255) / 256, 256>>>(attn, cls_tok, pos_emb, x);
    }

    const int NELEM = BATCH * HEADS * TOK * DHD;
    for (int l = 0; l < 12; l++) {
        // --- attention sub-block ---
        ln_kernel<<<ROWS, 256>>>(x, ln1_w + (size_t)l * DIM, ln1_b + (size_t)l * DIM, h);
        launch_gemm(h, DIM, qkv_w + (size_t)l * QKVD * DIM, qkv_b + (size_t)l * QKVD,
                    nullptr, qkv, QKVD, ROWS, QKVD, DIM, 0);
        reorder_qkv<<<(NELEM + 255) / 256, 256>>>(qkv, q, k, v);
        attn_kernel<<<BATCH * HEADS, 256, ATTN_SMEM>>>(q, k, v, attn);
        launch_gemm(attn, DIM, proj_w + (size_t)l * DIM * DIM, proj_b + (size_t)l * DIM,
                    x, x, DIM, ROWS, DIM, DIM, 0);
        // --- MLP sub-block ---
        ln_kernel<<<ROWS, 256>>>(x, ln2_w + (size_t)l * DIM, ln2_b + (size_t)l * DIM, h);
        launch_gemm(h, DIM, ff1_w + (size_t)l * FFD * DIM, ff1_b + (size_t)l * FFD,
                    nullptr, ff, FFD, ROWS, FFD, DIM, 1 /*gelu*/);
        launch_gemm(ff, FFD, ff2_w + (size_t)l * DIM * FFD, ff2_b + (size_t)l * DIM,
                    x, x, DIM, ROWS, DIM, FFD, 0);
    }

    // head: latent = x[:, 0, :]  (row stride TOK*DIM)
    launch_gemm(x, TOK * DIM, head1_w, head1_b, nullptr, ff, FFD,
                BATCH, FFD, DIM, 2 /*tanh*/);
    launch_gemm(ff, FFD, head2_w, head2_b, nullptr, out, NCLSD,
                BATCH, NCLSD, FFD, 0);
}

// round 4
// speedup vs baseline: 1.9608x; 1.9588x over previous
#include <cuda_runtime.h>
#include <cuda_fp16.h>
#include <math.h>
#include <stdint.h>

#define BATCH 32
#define TOK 197
#define ROWS (BATCH*TOK)
#define MPAD 6400
#define DIM 768
#define HEADS 12
#define DHD 64
#define FFD 3072
#define QKVD 2304
#define NPATCH 196
#define PATCH_ROWS (BATCH*NPATCH)
#define NCLSD 1000
#define KP_D (3*DIM)
#define KP_F (3*FFD)

__device__ float  g_x   [ROWS*DIM];
__device__ float  g_qkv [ROWS*QKVD];
__device__ float  g_q   [BATCH*HEADS*TOK*DHD];
__device__ float  g_kk  [BATCH*HEADS*TOK*DHD];
__device__ float  g_v   [BATCH*HEADS*TOK*DHD];
__device__ float  g_tok [PATCH_ROWS*DIM];
__device__ float  g_hh  [BATCH*FFD];
__device__ __align__(128) __half g_a16 [MPAD*KP_D];
__device__ __align__(128) __half g_f16 [(size_t)MPAD*KP_F];
__device__ __align__(128) __half g_wp16  [DIM*KP_D];
__device__ __align__(128) __half g_wqkv16[(size_t)12*QKVD*KP_D];
__device__ __align__(128) __half g_wpr16 [(size_t)12*DIM*KP_D];
__device__ __align__(128) __half g_wf1_16[(size_t)12*FFD*KP_D];
__device__ __align__(128) __half g_wf2_16[(size_t)12*DIM*KP_F];

__device__ __forceinline__ uint32_t smem_u32(const void* p) {
    uint32_t a;
    asm("{ .reg .u64 t; cvta.to.shared.u64 t, %1; cvt.u32.u64 %0, t; }" : "=r"(a) : "l"(p));
    return a;
}
__device__ __forceinline__ void cp_async16(uint32_t s, const void* g) {
    asm volatile("cp.async.cg.shared.global [%0], [%1], 16;\n" :: "r"(s), "l"(g));
}
#define CP_COMMIT() asm volatile("cp.async.commit_group;\n" ::: "memory")
#define CP_WAIT(n)  asm volatile("cp.async.wait_group %0;\n" :: "n"(n) : "memory")

__device__ __forceinline__ void ldsm_x4(uint32_t& r0, uint32_t& r1, uint32_t& r2, uint32_t& r3,
                                        uint32_t addr) {
    asm volatile("ldmatrix.sync.aligned.m8n8.x4.shared.b16 {%0,%1,%2,%3}, [%4];"
                 : "=r"(r0), "=r"(r1), "=r"(r2), "=r"(r3) : "r"(addr));
}
__device__ __forceinline__ void mma16816(float* c, const uint32_t* a, const uint32_t* b) {
    asm volatile("mma.sync.aligned.m16n8k16.row.col.f32.f16.f16.f32 "
        "{%0,%1,%2,%3}, {%4,%5,%6,%7}, {%8,%9}, {%0,%1,%2,%3};"
        : "+f"(c[0]), "+f"(c[1]), "+f"(c[2]), "+f"(c[3])
        : "r"(a[0]), "r"(a[1]), "r"(a[2]), "r"(a[3]), "r"(b[0]), "r"(b[1]));
}
__device__ __forceinline__ float gelu_f(float v) {
    return 0.5f * v * (1.0f + erff(v * 0.70710678118654752f));
}

// ===== split-fp16 HMMA GEMM: tile 128x128x32, 4 stages, 256 threads =====
// mode 0: fp32 = bias;  mode 1: fp32 = bias + res;  mode 2: gelu -> split fp16 [hi|lo|hi]
#define HSTAGE 16384          // (128*32 + 128*32) halves * 2B
#define HG_SMEM (4*HSTAGE)

__global__ __launch_bounds__(256) void hgemm(
    const __half* __restrict__ A, const __half* __restrict__ B, int Kp,
    const float* __restrict__ bias, const float* __restrict__ res,
    float* __restrict__ outF, __half* __restrict__ out16,
    int ldc, int M, int mode)
{
    extern __shared__ char smraw[];
    uint32_t smb = smem_u32(smraw);
    int tid = threadIdx.x;
    int lane = tid & 31, wid = tid >> 5;
    int warp_m = wid & 1, warp_n = wid >> 1;          // 2 x 4 warps
    int row0 = blockIdx.y * 128, col0 = blockIdx.x * 128;

    // cp.async chunk mapping (each thread: 2 A chunks + 2 B chunks of 16B)
    // chunkid -> row = id>>2, c = id&3 ; smem slot = row*64 + ((c ^ ((row>>1)&3))<<4)
    int a_row0 = (tid + 0)   >> 2, a_c0 = (tid + 0)   & 3;
    int a_row1 = (tid + 256) >> 2, a_c1 = (tid + 256) & 3;
    uint32_t a_s0 = a_row0 * 64 + ((a_c0 ^ ((a_row0 >> 1) & 3)) << 4);
    uint32_t a_s1 = a_row1 * 64 + ((a_c1 ^ ((a_row1 >> 1) & 3)) << 4);

    // ldmatrix per-lane geometry
    int g = lane >> 3, l = lane & 7;
    // A frags: row = warp_m*64 + mi*16 + (g&1)*8 + l ; chunk = ks*2 + (g>>1)
    uint32_t a_r64[4], a_rx[4];
#pragma unroll
    for (int mi = 0; mi < 4; mi++) {
        int r = warp_m * 64 + mi * 16 + (g & 1) * 8 + l;
        a_r64[mi] = r * 64; a_rx[mi] = (r >> 1) & 3;
    }
    // B frags: row = warp_n*32 + j2*16 + (g>>1)*8 + l ; chunk = ks*2 + (g&1)
    uint32_t b_r64[2], b_rx[2];
#pragma unroll
    for (int j2 = 0; j2 < 2; j2++) {
        int r = warp_n * 32 + j2 * 16 + (g >> 1) * 8 + l;
        b_r64[j2] = r * 64; b_rx[j2] = (r >> 1) & 3;
    }

    float acc[4][4][4];
#pragma unroll
    for (int mi = 0; mi < 4; mi++)
#pragma unroll
        for (int nj = 0; nj < 4; nj++)
#pragma unroll
            for (int q = 0; q < 4; q++) acc[mi][nj][q] = 0.f;

    const int KT = Kp >> 5;
    const size_t strA = (size_t)Kp, strB = (size_t)Kp;

#define LOAD_STAGE(s, kb) do { \
    uint32_t sa = smb + (uint32_t)(s) * HSTAGE; \
    const __half* gA = A + (size_t)(row0) * strA + (size_t)(kb) * 32; \
    cp_async16(sa + a_s0, gA + (size_t)a_row0 * strA + a_c0 * 8); \
    cp_async16(sa + a_s1, gA + (size_t)a_row1 * strA + a_c1 * 8); \
    uint32_t sbb = sa + 8192u; \
    const __half* gB = B + (size_t)(col0) * strB + (size_t)(kb) * 32; \
    cp_async16(sbb + a_s0, gB + (size_t)a_row0 * strB + a_c0 * 8); \
    cp_async16(sbb + a_s1, gB + (size_t)a_row1 * strB + a_c1 * 8); \
} while (0)

#pragma unroll
    for (int s = 0; s < 3; s++) { LOAD_STAGE(s, s); CP_COMMIT(); }

    for (int i = 0; i < KT; i++) {
        CP_WAIT(2);
        __syncthreads();
        int cur = i & 3;
        if (i + 3 < KT) LOAD_STAGE((i + 3) & 3, i + 3);
        CP_COMMIT();

        uint32_t abase = smb + (uint32_t)cur * HSTAGE;
        uint32_t bbase = abase + 8192u;
#pragma unroll
        for (int ks = 0; ks < 2; ks++) {
            uint32_t af[4][4], bf[4][2];
#pragma unroll
            for (int mi = 0; mi < 4; mi++) {
                uint32_t ch = (uint32_t)(ks * 2 + (g >> 1));
                uint32_t addr = abase + a_r64[mi] + ((ch ^ a_rx[mi]) << 4);
                ldsm_x4(af[mi][0], af[mi][1], af[mi][2], af[mi][3], addr);
            }
#pragma unroll
            for (int j2 = 0; j2 < 2; j2++) {
                uint32_t ch = (uint32_t)(ks * 2 + (g & 1));
                uint32_t addr = bbase + b_r64[j2] + ((ch ^ b_rx[j2]) << 4);
                ldsm_x4(bf[j2 * 2][0], bf[j2 * 2][1], bf[j2 * 2 + 1][0], bf[j2 * 2 + 1][1], addr);
            }
#pragma unroll
            for (int mi = 0; mi < 4; mi++)
#pragma unroll
                for (int nj = 0; nj < 4; nj++)
                    mma16816(acc[mi][nj], af[mi], bf[nj]);
        }
    }

    // ---------------- epilogue ----------------
    int qrow = lane >> 2, qcol = (lane & 3) * 2;
#pragma unroll
    for (int mi = 0; mi < 4; mi++) {
        int rbase = row0 + warp_m * 64 + mi * 16 + qrow;
#pragma unroll
        for (int half = 0; half < 2; half++) {
            int r = rbase + half * 8;
            if (r >= M) continue;
#pragma unroll
            for (int nj = 0; nj < 4; nj++) {
                int c = col0 + warp_n * 32 + nj * 8 + qcol;
                float v0 = acc[mi][nj][half * 2 + 0] + __ldg(bias + c);
                float v1 = acc[mi][nj][half * 2 + 1] + __ldg(bias + c + 1);
                if (mode == 2) {
                    float g0 = gelu_f(v0), g1 = gelu_f(v1);
                    __half h0 = __float2half(g0), h1 = __float2half(g1);
                    __half l0 = __float2half(g0 - __half2float(h0));
                    __half l1 = __float2half(g1 - __half2float(h1));
                    __half2 hv = __halves2half2(h0, h1);
                    __half2 lv = __halves2half2(l0, l1);
                    __half* o = out16 + (size_t)r * (3 * ldc) + c;
                    *(__half2*)(o)           = hv;
                    *(__half2*)(o + ldc)     = lv;
                    *(__half2*)(o + 2 * ldc) = hv;
                } else {
                    float* o = outF + (size_t)r * ldc + c;
                    if (mode == 1) {
                        const float* rr = res + (size_t)r * ldc + c;
                        v0 += rr[0]; v1 += rr[1];
                    }
                    float2 vv = make_float2(v0, v1);
                    *(float2*)o = vv;
                }
            }
        }
    }
}

// ===== helpers =====
__global__ void convert_w(const float* __restrict__ W, __half* __restrict__ W16,
                          int K, long total)
{
    long idx = (long)blockIdx.x * blockDim.x + threadIdx.x;
    if (idx >= total) return;
    long row = idx / K; int k = (int)(idx - row * K);
    float v = W[idx];
    __half hi = __float2half(v);
    __half* dst = W16 + row * (3L * K);
    dst[k] = hi; dst[K + k] = hi; dst[2L * K + k] = __float2half(v - __half2float(hi));
}

__global__ __launch_bounds__(256) void ln_split(
    const float* __restrict__ x, const float* __restrict__ w,
    const float* __restrict__ b, __half* __restrict__ y16)
{
    int row = blockIdx.x;
    const float* xr = x + (size_t)row * DIM;
    __shared__ float red[256];
    int tid = threadIdx.x;
    float s = 0.f;
    for (int i = tid; i < DIM; i += 256) s += xr[i];
    red[tid] = s; __syncthreads();
    for (int o = 128; o > 0; o >>= 1) { if (tid < o) red[tid] += red[tid + o]; __syncthreads(); }
    float mean = red[0] * (1.0f / DIM);
    __syncthreads();
    float s2 = 0.f;
    for (int i = tid; i < DIM; i += 256) { float d = xr[i] - mean; s2 += d * d; }
    red[tid] = s2; __syncthreads();
    for (int o = 128; o > 0; o >>= 1) { if (tid < o) red[tid] += red[tid + o]; __syncthreads(); }
    float inv = rsqrtf(red[0] * (1.0f / DIM) + 1e-5f);
    __half* yr = y16 + (size_t)row * KP_D;
    for (int i = tid; i < DIM; i += 256) {
        float v = (xr[i] - mean) * inv * w[i] + b[i];
        __half hi = __float2half(v);
        yr[i] = hi;
        yr[DIM + i] = __float2half(v - __half2float(hi));
        yr[2 * DIM + i] = hi;
    }
}

__global__ void im2col_split(const float* __restrict__ img, __half* __restrict__ a16)
{
    int idx = blockIdx.x * blockDim.x + threadIdx.x;
    if (idx >= PATCH_ROWS * DIM) return;
    int e = idx % DIM;
    int m = idx / DIM;
    int b = m / NPATCH, p = m % NPATCH;
    int gr = p / 14, gc = p % 14;
    int c = e % 3;
    int pp = e / 3;
    int pr = pp / 16, pc = pp % 16;
    float v = img[(((size_t)b * 3 + c) * 224 + gr * 16 + pr) * 224 + gc * 16 + pc];
    __half hi = __float2half(v);
    __half* dst = a16 + (size_t)m * KP_D;
    dst[e] = hi;
    dst[DIM + e] = __float2half(v - __half2float(hi));
    dst[2 * DIM + e] = hi;
}

__global__ void assemble_kernel(const float* __restrict__ tokens,
                                const float* __restrict__ cls,
                                const float* __restrict__ pos,
                                float* __restrict__ x)
{
    int idx = blockIdx.x * blockDim.x + threadIdx.x;
    if (idx >= ROWS * DIM) return;
    int d = idx % DIM;
    int r = idx / DIM;
    int b = r / TOK, n = r % TOK;
    float v = (n == 0) ? cls[d] : tokens[((size_t)b * NPATCH + (n - 1)) * DIM + d];
    x[idx] = v + pos[(size_t)n * DIM + d];
}

__global__ void reorder_qkv(const float* __restrict__ qkv,
                            float* __restrict__ Q, float* __restrict__ K, float* __restrict__ V)
{
    int idx = blockIdx.x * blockDim.x + threadIdx.x;
    const int total = BATCH * HEADS * TOK * DHD;
    if (idx >= total) return;
    int d = idx & 63;
    int n = (idx >> 6) % TOK;
    int h = (idx >> 6) / TOK % HEADS;
    int b = idx / (64 * TOK * HEADS);
    const float* src = qkv + ((size_t)(b * TOK + n)) * QKVD + h * 192 + d * 3;
    Q[idx] = src[0]; K[idx] = src[1]; V[idx] = src[2];
}

__global__ __launch_bounds__(256) void attn_kernel(
    const float* __restrict__ Q, const float* __restrict__ K,
    const float* __restrict__ V, __half* __restrict__ a16)
{
    extern __shared__ float sm[];
    float* ks = sm;
    float* vs = sm + TOK * 65;
    __shared__ float qs[DHD];
    __shared__ float sc[TOK];
    __shared__ float red[256];

    int bh = blockIdx.x;
    int b = bh / HEADS, h = bh % HEADS;
    int tid = threadIdx.x;
    const float* Qb = Q + (size_t)bh * TOK * DHD;
    const float* Kb = K + (size_t)bh * TOK * DHD;
    const float* Vb = V + (size_t)bh * TOK * DHD;

    for (int i = tid; i < TOK * DHD; i += 256) {
        int n = i >> 6, d = i & 63;
        ks[n * 65 + d] = Kb[i];
        vs[n * 65 + d] = Vb[i];
    }
    __syncthreads();

    for (int nq = 0; nq < TOK; nq++) {
        if (tid < DHD) qs[tid] = Qb[(size_t)nq * DHD + tid];
        __syncthreads();
        if (tid < TOK) {
            const float* kr = &ks[tid * 65];
            float s = 0.f;
#pragma unroll
            for (int d = 0; d < DHD; d++) s += kr[d] * qs[d];
            sc[tid] = s * 0.125f;
        }
        __syncthreads();
        red[tid] = (tid < TOK) ? sc[tid] : -1e30f;
        __syncthreads();
        for (int o = 128; o > 0; o >>= 1) { if (tid < o) red[tid] = fmaxf(red[tid], red[tid + o]); __syncthreads(); }
        float mx = red[0];
        __syncthreads();
        float p = (tid < TOK) ? expf(sc[tid] - mx) : 0.f;
        if (tid < TOK) sc[tid] = p;
        red[tid] = p;
        __syncthreads();
        for (int o = 128; o > 0; o >>= 1) { if (tid < o) red[tid] += red[tid + o]; __syncthreads(); }
        float inv = 1.0f / red[0];
        __syncthreads();
        int gg = tid >> 6, d = tid & 63;
        float acc = 0.f;
        for (int kk = gg; kk < TOK; kk += 4) acc += sc[kk] * vs[kk * 65 + d];
        red[tid] = acc;
        __syncthreads();
        if (tid < DHD) {
            float o = (red[tid] + red[tid + 64] + red[tid + 128] + red[tid + 192]) * inv;
            size_t base = ((size_t)(b * TOK + nq)) * KP_D + h * DHD + tid;
            __half hh = __float2half(o);
            a16[base] = hh;
            a16[base + DIM] = __float2half(o - __half2float(hh));
            a16[base + 2 * DIM] = hh;
        }
        __syncthreads();
    }
}

// fp32 SGEMM for the tiny head (M=32)
__global__ __launch_bounds__(256) void sgemm(
    const float* __restrict__ A, int lda,
    const float* __restrict__ W, const float* __restrict__ bias,
    float* __restrict__ C, int ldc, int M, int N, int K, int act)
{
    __shared__ float As[16][128];
    __shared__ float Bs[16][64];
    int tid = threadIdx.x;
    int tx = tid & 15, ty = tid >> 4;
    int row0 = blockIdx.y * 128;
    int col0 = blockIdx.x * 64;
    float acc[8][4];
#pragma unroll
    for (int i = 0; i < 8; i++)
#pragma unroll
        for (int j = 0; j < 4; j++) acc[i][j] = 0.f;
    for (int k0 = 0; k0 < K; k0 += 16) {
#pragma unroll
        for (int i = 0; i < 2; i++) {
            int idx = tid + i * 256;
            int r = idx >> 2, c = (idx & 3) << 2;
            int gr = row0 + r;
            float4 v = make_float4(0.f, 0.f, 0.f, 0.f);
            if (gr < M) v = *(const float4*)(A + (size_t)gr * lda + k0 + c);
            As[c + 0][r] = v.x; As[c + 1][r] = v.y; As[c + 2][r] = v.z; As[c + 3][r] = v.w;
        }
        {
            int n = tid >> 2, c = (tid & 3) << 2;
            int gn = col0 + n;
            float4 v = make_float4(0.f, 0.f, 0.f, 0.f);
            if (gn < N) v = *(const float4*)(W + (size_t)gn * K + k0 + c);
            Bs[c + 0][n] = v.x; Bs[c + 1][n] = v.y; Bs[c + 2][n] = v.z; Bs[c + 3][n] = v.w;
        }
        __syncthreads();
#pragma unroll
        for (int kk = 0; kk < 16; kk++) {
            float4 a0 = *(const float4*)&As[kk][ty * 8];
            float4 a1 = *(const float4*)&As[kk][ty * 8 + 4];
            float4 bb = *(const float4*)&Bs[kk][tx * 4];
            float av[8] = {a0.x, a0.y, a0.z, a0.w, a1.x, a1.y, a1.z, a1.w};
            float bv[4] = {bb.x, bb.y, bb.z, bb.w};
#pragma unroll
            for (int i = 0; i < 8; i++)
#pragma unroll
                for (int j = 0; j < 4; j++) acc[i][j] += av[i] * bv[j];
        }
        __syncthreads();
    }
#pragma unroll
    for (int i = 0; i < 8; i++) {
        int gr = row0 + ty * 8 + i;
        if (gr >= M) continue;
#pragma unroll
        for (int j = 0; j < 4; j++) {
            int gn = col0 + tx * 4 + j;
            if (gn >= N) continue;
            float v = acc[i][j];
            if (bias) v += bias[gn];
            if (act == 2) v = tanhf(v);
            C[(size_t)gr * ldc + gn] = v;
        }
    }
}

extern "C" void kernel_launch(void* const* d_in, const int* in_sizes, int n_in,
                              void* d_out, int out_size)
{
    const float* img     = (const float*)d_in[0];
    const float* patch_w = (const float*)d_in[1];
    const float* patch_b = (const float*)d_in[2];
    const float* cls_tok = (const float*)d_in[3];
    const float* pos_emb = (const float*)d_in[4];
    const float* ln1_w   = (const float*)d_in[5];
    const float* ln1_b   = (const float*)d_in[6];
    const float* qkv_w   = (const float*)d_in[7];
    const float* qkv_b   = (const float*)d_in[8];
    const float* proj_w  = (const float*)d_in[9];
    const float* proj_b  = (const float*)d_in[10];
    const float* ln2_w   = (const float*)d_in[11];
    const float* ln2_b   = (const float*)d_in[12];
    const float* ff1_w   = (const float*)d_in[13];
    const float* ff1_b   = (const float*)d_in[14];
    const float* ff2_w   = (const float*)d_in[15];
    const float* ff2_b   = (const float*)d_in[16];
    const float* head1_w = (const float*)d_in[17];
    const float* head1_b = (const float*)d_in[18];
    const float* head2_w = (const float*)d_in[19];
    const float* head2_b = (const float*)d_in[20];
    float* out = (float*)d_out;

    float *x, *qkv, *q, *k, *v, *tok, *hh;
    __half *a16, *f16, *wp, *wq, *wpr, *wf1, *wf2;
    cudaGetSymbolAddress((void**)&x,   g_x);
    cudaGetSymbolAddress((void**)&qkv, g_qkv);
    cudaGetSymbolAddress((void**)&q,   g_q);
    cudaGetSymbolAddress((void**)&k,   g_kk);
    cudaGetSymbolAddress((void**)&v,   g_v);
    cudaGetSymbolAddress((void**)&tok, g_tok);
    cudaGetSymbolAddress((void**)&hh,  g_hh);
    cudaGetSymbolAddress((void**)&a16, g_a16);
    cudaGetSymbolAddress((void**)&f16, g_f16);
    cudaGetSymbolAddress((void**)&wp,  g_wp16);
    cudaGetSymbolAddress((void**)&wq,  g_wqkv16);
    cudaGetSymbolAddress((void**)&wpr, g_wpr16);
    cudaGetSymbolAddress((void**)&wf1, g_wf1_16);
    cudaGetSymbolAddress((void**)&wf2, g_wf2_16);

    cudaFuncSetAttribute(hgemm, cudaFuncAttributeMaxDynamicSharedMemorySize, HG_SMEM);
    const int ATTN_SMEM = 2 * TOK * 65 * (int)sizeof(float);
    cudaFuncSetAttribute(attn_kernel, cudaFuncAttributeMaxDynamicSharedMemorySize, ATTN_SMEM);

    // weights -> split fp16
    {
        long t;
        t = (long)DIM * DIM;  convert_w<<<(unsigned)((t + 255) / 256), 256>>>(patch_w, wp,  DIM, t);
        t = 12L * QKVD * DIM; convert_w<<<(unsigned)((t + 255) / 256), 256>>>(qkv_w,   wq,  DIM, t);
        t = 12L * DIM * DIM;  convert_w<<<(unsigned)((t + 255) / 256), 256>>>(proj_w,  wpr, DIM, t);
        t = 12L * FFD * DIM;  convert_w<<<(unsigned)((t + 255) / 256), 256>>>(ff1_w,   wf1, DIM, t);
        t = 12L * DIM * FFD;  convert_w<<<(unsigned)((t + 255) / 256), 256>>>(ff2_w,   wf2, FFD, t);
    }

    // patch embed
    {
        int tot = PATCH_ROWS * DIM;
        im2col_split<<<(tot + 255) / 256, 256>>>(img, a16);
        hgemm<<<dim3(6, 49), 256, HG_SMEM>>>(a16, wp, KP_D, patch_b, (const float*)0,
                                             tok, (__half*)0, DIM, PATCH_ROWS, 0);
        int tot2 = ROWS * DIM;
        assemble_kernel<<<(tot2 + 255) / 256, 256>>>(tok, cls_tok, pos_emb, x);
    }

    const int NELEM = BATCH * HEADS * TOK * DHD;
    for (int l = 0; l < 12; l++) {
        ln_split<<<ROWS, 256>>>(x, ln1_w + (size_t)l * DIM, ln1_b + (size_t)l * DIM, a16);
        hgemm<<<dim3(18, 50), 256, HG_SMEM>>>(a16, wq + (size_t)l * QKVD * KP_D, KP_D,
                                              qkv_b + (size_t)l * QKVD, (const float*)0,
                                              qkv, (__half*)0, QKVD, ROWS, 0);
        reorder_qkv<<<(NELEM + 255) / 256, 256>>>(qkv, q, k, v);
        attn_kernel<<<BATCH * HEADS, 256, ATTN_SMEM>>>(q, k, v, a16);
        hgemm<<<dim3(6, 50), 256, HG_SMEM>>>(a16, wpr + (size_t)l * DIM * KP_D, KP_D,
                                             proj_b + (size_t)l * DIM, x,
                                             x, (__half*)0, DIM, ROWS, 1);
        ln_split<<<ROWS, 256>>>(x, ln2_w + (size_t)l * DIM, ln2_b + (size_t)l * DIM, a16);
        hgemm<<<dim3(24, 50), 256, HG_SMEM>>>(a16, wf1 + (size_t)l * FFD * KP_D, KP_D,
                                              ff1_b + (size_t)l * FFD, (const float*)0,
                                              (float*)0, f16, FFD, ROWS, 2);
        hgemm<<<dim3(6, 50), 256, HG_SMEM>>>(f16, wf2 + (size_t)l * DIM * KP_F, KP_F,
                                             ff2_b + (size_t)l * DIM, x,
                                             x, (__half*)0, DIM, ROWS, 1);
    }

    // head (fp32, tiny M)
    sgemm<<<dim3(48, 1), 256>>>(x, TOK * DIM, head1_w, head1_b, hh, FFD, BATCH, FFD, DIM, 2);
    sgemm<<<dim3(16, 1), 256>>>(hh, FFD, head2_w, head2_b, out, NCLSD, BATCH, NCLSD, FFD, 0);
}

// round 5
// speedup vs baseline: 3.1474x; 1.6051x over previous
#include <cuda_runtime.h>
#include <cuda_fp16.h>
#include <math.h>
#include <stdint.h>

#define BATCH 32
#define TOK 197
#define ROWS (BATCH*TOK)
#define MPAD 6400
#define DIM 768
#define HEADS 12
#define DHD 64
#define FFD 3072
#define QKVD 2304
#define NPATCH 196
#define PATCH_ROWS (BATCH*NPATCH)
#define NCLSD 1000
#define KP_D (3*DIM)
#define KP_F (3*FFD)

__device__ float  g_x   [ROWS*DIM];
__device__ float  g_qkv [ROWS*QKVD];
__device__ float  g_q   [BATCH*HEADS*TOK*DHD];
__device__ float  g_kk  [BATCH*HEADS*TOK*DHD];
__device__ float  g_v   [BATCH*HEADS*TOK*DHD];
__device__ float  g_tok [PATCH_ROWS*DIM];
__device__ float  g_hh  [BATCH*FFD];
__device__ __align__(128) __half g_a16 [MPAD*KP_D];
__device__ __align__(128) __half g_f16 [(size_t)MPAD*KP_F];
__device__ __align__(128) __half g_wp16  [DIM*KP_D];
__device__ __align__(128) __half g_wqkv16[(size_t)12*QKVD*KP_D];
__device__ __align__(128) __half g_wpr16 [(size_t)12*DIM*KP_D];
__device__ __align__(128) __half g_wf1_16[(size_t)12*FFD*KP_D];
__device__ __align__(128) __half g_wf2_16[(size_t)12*DIM*KP_F];

__device__ __forceinline__ uint32_t smem_u32(const void* p) {
    uint32_t a;
    asm("{ .reg .u64 t; cvta.to.shared.u64 t, %1; cvt.u32.u64 %0, t; }" : "=r"(a) : "l"(p));
    return a;
}
__device__ __forceinline__ void cp_async16(uint32_t s, const void* g) {
    asm volatile("cp.async.cg.shared.global [%0], [%1], 16;\n" :: "r"(s), "l"(g));
}
#define CP_COMMIT() asm volatile("cp.async.commit_group;\n" ::: "memory")
#define CP_WAIT(n)  asm volatile("cp.async.wait_group %0;\n" :: "n"(n) : "memory")

__device__ __forceinline__ void ldsm_x4(uint32_t& r0, uint32_t& r1, uint32_t& r2, uint32_t& r3,
                                        uint32_t addr) {
    asm volatile("ldmatrix.sync.aligned.m8n8.x4.shared.b16 {%0,%1,%2,%3}, [%4];"
                 : "=r"(r0), "=r"(r1), "=r"(r2), "=r"(r3) : "r"(addr));
}
__device__ __forceinline__ void mma16816(float* c, const uint32_t* a, const uint32_t* b) {
    asm volatile("mma.sync.aligned.m16n8k16.row.col.f32.f16.f16.f32 "
        "{%0,%1,%2,%3}, {%4,%5,%6,%7}, {%8,%9}, {%0,%1,%2,%3};"
        : "+f"(c[0]), "+f"(c[1]), "+f"(c[2]), "+f"(c[3])
        : "r"(a[0]), "r"(a[1]), "r"(a[2]), "r"(a[3]), "r"(b[0]), "r"(b[1]));
}
__device__ __forceinline__ float gelu_f(float v) {
    return 0.5f * v * (1.0f + erff(v * 0.70710678118654752f));
}

// ===== split-fp16 HMMA GEMM: tile 128x128x32, 4 stages, 256 threads, 2 CTAs/SM =====
#define HSTAGE 16384
#define HG_SMEM (4*HSTAGE)

__global__ __launch_bounds__(256, 2) void hgemm(
    const __half* __restrict__ A, const __half* __restrict__ B, int Kp,
    const float* __restrict__ bias, const float* __restrict__ res,
    float* __restrict__ outF, __half* __restrict__ out16,
    int ldc, int M, int mode)
{
    extern __shared__ char smraw[];
    uint32_t smb = smem_u32(smraw);
    int tid = threadIdx.x;
    int lane = tid & 31, wid = tid >> 5;
    int warp_m = wid & 1, warp_n = wid >> 1;
    int row0 = blockIdx.y * 128, col0 = blockIdx.x * 128;

    int a_row0 = (tid + 0)   >> 2, a_c0 = (tid + 0)   & 3;
    int a_row1 = (tid + 256) >> 2, a_c1 = (tid + 256) & 3;
    uint32_t a_s0 = a_row0 * 64 + ((a_c0 ^ ((a_row0 >> 1) & 3)) << 4);
    uint32_t a_s1 = a_row1 * 64 + ((a_c1 ^ ((a_row1 >> 1) & 3)) << 4);

    int g = lane >> 3, l = lane & 7;
    uint32_t a_r64[4], a_rx[4];
#pragma unroll
    for (int mi = 0; mi < 4; mi++) {
        int r = warp_m * 64 + mi * 16 + (g & 1) * 8 + l;
        a_r64[mi] = r * 64; a_rx[mi] = (r >> 1) & 3;
    }
    uint32_t b_r64[2], b_rx[2];
#pragma unroll
    for (int j2 = 0; j2 < 2; j2++) {
        int r = warp_n * 32 + j2 * 16 + (g >> 1) * 8 + l;
        b_r64[j2] = r * 64; b_rx[j2] = (r >> 1) & 3;
    }

    float acc[4][4][4];
#pragma unroll
    for (int mi = 0; mi < 4; mi++)
#pragma unroll
        for (int nj = 0; nj < 4; nj++)
#pragma unroll
            for (int q = 0; q < 4; q++) acc[mi][nj][q] = 0.f;

    const int KT = Kp >> 5;
    const size_t strA = (size_t)Kp, strB = (size_t)Kp;

#define LOAD_STAGE(s, kb) do { \
    uint32_t sa = smb + (uint32_t)(s) * HSTAGE; \
    const __half* gA = A + (size_t)(row0) * strA + (size_t)(kb) * 32; \
    cp_async16(sa + a_s0, gA + (size_t)a_row0 * strA + a_c0 * 8); \
    cp_async16(sa + a_s1, gA + (size_t)a_row1 * strA + a_c1 * 8); \
    uint32_t sbb = sa + 8192u; \
    const __half* gB = B + (size_t)(col0) * strB + (size_t)(kb) * 32; \
    cp_async16(sbb + a_s0, gB + (size_t)a_row0 * strB + a_c0 * 8); \
    cp_async16(sbb + a_s1, gB + (size_t)a_row1 * strB + a_c1 * 8); \
} while (0)

#pragma unroll
    for (int s = 0; s < 3; s++) { LOAD_STAGE(s, s); CP_COMMIT(); }

    for (int i = 0; i < KT; i++) {
        CP_WAIT(2);
        __syncthreads();
        int cur = i & 3;
        if (i + 3 < KT) LOAD_STAGE((i + 3) & 3, i + 3);
        CP_COMMIT();

        uint32_t abase = smb + (uint32_t)cur * HSTAGE;
        uint32_t bbase = abase + 8192u;
#pragma unroll
        for (int ks = 0; ks < 2; ks++) {
            uint32_t af[4][4], bf[4][2];
#pragma unroll
            for (int mi = 0; mi < 4; mi++) {
                uint32_t ch = (uint32_t)(ks * 2 + (g >> 1));
                uint32_t addr = abase + a_r64[mi] + ((ch ^ a_rx[mi]) << 4);
                ldsm_x4(af[mi][0], af[mi][1], af[mi][2], af[mi][3], addr);
            }
#pragma unroll
            for (int j2 = 0; j2 < 2; j2++) {
                uint32_t ch = (uint32_t)(ks * 2 + (g & 1));
                uint32_t addr = bbase + b_r64[j2] + ((ch ^ b_rx[j2]) << 4);
                ldsm_x4(bf[j2 * 2][0], bf[j2 * 2][1], bf[j2 * 2 + 1][0], bf[j2 * 2 + 1][1], addr);
            }
#pragma unroll
            for (int mi = 0; mi < 4; mi++)
#pragma unroll
                for (int nj = 0; nj < 4; nj++)
                    mma16816(acc[mi][nj], af[mi], bf[nj]);
        }
    }

    int qrow = lane >> 2, qcol = (lane & 3) * 2;
#pragma unroll
    for (int mi = 0; mi < 4; mi++) {
        int rbase = row0 + warp_m * 64 + mi * 16 + qrow;
#pragma unroll
        for (int half = 0; half < 2; half++) {
            int r = rbase + half * 8;
            if (r >= M) continue;
#pragma unroll
            for (int nj = 0; nj < 4; nj++) {
                int c = col0 + warp_n * 32 + nj * 8 + qcol;
                float v0 = acc[mi][nj][half * 2 + 0] + __ldg(bias + c);
                float v1 = acc[mi][nj][half * 2 + 1] + __ldg(bias + c + 1);
                if (mode == 2) {
                    float g0 = gelu_f(v0), g1 = gelu_f(v1);
                    __half h0 = __float2half(g0), h1 = __float2half(g1);
                    __half l0 = __float2half(g0 - __half2float(h0));
                    __half l1 = __float2half(g1 - __half2float(h1));
                    __half2 hv = __halves2half2(h0, h1);
                    __half2 lv = __halves2half2(l0, l1);
                    __half* o = out16 + (size_t)r * (3 * ldc) + c;
                    *(__half2*)(o)           = hv;
                    *(__half2*)(o + ldc)     = lv;
                    *(__half2*)(o + 2 * ldc) = hv;
                } else {
                    float* o = outF + (size_t)r * ldc + c;
                    if (mode == 1) {
                        const float* rr = res + (size_t)r * ldc + c;
                        v0 += rr[0]; v1 += rr[1];
                    }
                    float2 vv = make_float2(v0, v1);
                    *(float2*)o = vv;
                }
            }
        }
    }
}

// ===== helpers =====
__global__ void convert_w(const float* __restrict__ W, __half* __restrict__ W16,
                          int K, long total)
{
    long idx = (long)blockIdx.x * blockDim.x + threadIdx.x;
    if (idx >= total) return;
    long row = idx / K; int k = (int)(idx - row * K);
    float v = W[idx];
    __half hi = __float2half(v);
    __half* dst = W16 + row * (3L * K);
    dst[k] = hi; dst[K + k] = hi; dst[2L * K + k] = __float2half(v - __half2float(hi));
}

__global__ __launch_bounds__(256) void ln_split(
    const float* __restrict__ x, const float* __restrict__ w,
    const float* __restrict__ b, __half* __restrict__ y16)
{
    int row = blockIdx.x;
    const float* xr = x + (size_t)row * DIM;
    __shared__ float red[256];
    int tid = threadIdx.x;
    float s = 0.f;
    for (int i = tid; i < DIM; i += 256) s += xr[i];
    red[tid] = s; __syncthreads();
    for (int o = 128; o > 0; o >>= 1) { if (tid < o) red[tid] += red[tid + o]; __syncthreads(); }
    float mean = red[0] * (1.0f / DIM);
    __syncthreads();
    float s2 = 0.f;
    for (int i = tid; i < DIM; i += 256) { float d = xr[i] - mean; s2 += d * d; }
    red[tid] = s2; __syncthreads();
    for (int o = 128; o > 0; o >>= 1) { if (tid < o) red[tid] += red[tid + o]; __syncthreads(); }
    float inv = rsqrtf(red[0] * (1.0f / DIM) + 1e-5f);
    __half* yr = y16 + (size_t)row * KP_D;
    for (int i = tid; i < DIM; i += 256) {
        float v = (xr[i] - mean) * inv * w[i] + b[i];
        __half hi = __float2half(v);
        yr[i] = hi;
        yr[DIM + i] = __float2half(v - __half2float(hi));
        yr[2 * DIM + i] = hi;
    }
}

__global__ void im2col_split(const float* __restrict__ img, __half* __restrict__ a16)
{
    int idx = blockIdx.x * blockDim.x + threadIdx.x;
    if (idx >= PATCH_ROWS * DIM) return;
    int e = idx % DIM;
    int m = idx / DIM;
    int b = m / NPATCH, p = m % NPATCH;
    int gr = p / 14, gc = p % 14;
    int c = e % 3;
    int pp = e / 3;
    int pr = pp / 16, pc = pp % 16;
    float v = img[(((size_t)b * 3 + c) * 224 + gr * 16 + pr) * 224 + gc * 16 + pc];
    __half hi = __float2half(v);
    __half* dst = a16 + (size_t)m * KP_D;
    dst[e] = hi;
    dst[DIM + e] = __float2half(v - __half2float(hi));
    dst[2 * DIM + e] = hi;
}

__global__ void assemble_kernel(const float* __restrict__ tokens,
                                const float* __restrict__ cls,
                                const float* __restrict__ pos,
                                float* __restrict__ x)
{
    int idx = blockIdx.x * blockDim.x + threadIdx.x;
    if (idx >= ROWS * DIM) return;
    int d = idx % DIM;
    int r = idx / DIM;
    int b = r / TOK, n = r % TOK;
    float v = (n == 0) ? cls[d] : tokens[((size_t)b * NPATCH + (n - 1)) * DIM + d];
    x[idx] = v + pos[(size_t)n * DIM + d];
}

__global__ void reorder_qkv(const float* __restrict__ qkv,
                            float* __restrict__ Q, float* __restrict__ K, float* __restrict__ V)
{
    int idx = blockIdx.x * blockDim.x + threadIdx.x;
    const int total = BATCH * HEADS * TOK * DHD;
    if (idx >= total) return;
    int d = idx & 63;
    int n = (idx >> 6) % TOK;
    int h = (idx >> 6) / TOK % HEADS;
    int b = idx / (64 * TOK * HEADS);
    const float* src = qkv + ((size_t)(b * TOK + n)) * QKVD + h * 192 + d * 3;
    Q[idx] = src[0]; K[idx] = src[1]; V[idx] = src[2];
}

// ===== attention v2: warp-per-query, fp16 K/V in smem, shuffle softmax =====
#define ATT_PAD 33
#define ATT2_SMEM ((2*TOK*ATT_PAD + 8*ATT_PAD) * 4 + 8*200*4)

__global__ __launch_bounds__(256) void attn2(
    const float* __restrict__ Q, const float* __restrict__ K,
    const float* __restrict__ V, __half* __restrict__ a16)
{
    extern __shared__ char smraw[];
    __half2* ks2 = (__half2*)smraw;
    __half2* vs2 = ks2 + TOK * ATT_PAD;
    __half2* qs2 = vs2 + TOK * ATT_PAD;
    float*   sc  = (float*)(qs2 + 8 * ATT_PAD);

    int bh = blockIdx.x;
    int b = bh / HEADS, h = bh % HEADS;
    int tid = threadIdx.x, lane = tid & 31, w = tid >> 5;
    const float2* Qb = (const float2*)(Q + (size_t)bh * TOK * DHD);
    const float2* Kb = (const float2*)(K + (size_t)bh * TOK * DHD);
    const float2* Vb = (const float2*)(V + (size_t)bh * TOK * DHD);

    for (int i = tid; i < TOK * 32; i += 256) {
        int n = i >> 5, d2 = i & 31;
        float2 kv = Kb[i];
        float2 vv = Vb[i];
        ks2[n * ATT_PAD + d2] = __floats2half2_rn(kv.x, kv.y);
        vs2[n * ATT_PAD + d2] = __floats2half2_rn(vv.x, vv.y);
    }
    __syncthreads();

    float* scw = sc + w * 200;
    for (int base = 0; base < TOK; base += 8) {
        int nq = base + w;
        bool ok = (nq < TOK);
        if (ok) {
            float2 qv = Qb[(size_t)nq * 32 + lane];
            qs2[w * ATT_PAD + lane] = __floats2half2_rn(qv.x, qv.y);
        }
        __syncwarp();
        float mx = -1e30f;
        if (ok) {
            for (int kk = lane; kk < TOK; kk += 32) {
                float s = 0.f;
#pragma unroll
                for (int d2 = 0; d2 < 32; d2++) {
                    float2 kv = __half22float2(ks2[kk * ATT_PAD + d2]);
                    float2 qv = __half22float2(qs2[w * ATT_PAD + d2]);
                    s += kv.x * qv.x + kv.y * qv.y;
                }
                s *= 0.125f;
                scw[kk] = s;
                mx = fmaxf(mx, s);
            }
        }
#pragma unroll
        for (int o = 16; o > 0; o >>= 1) mx = fmaxf(mx, __shfl_xor_sync(0xffffffffu, mx, o));
        float sum = 0.f;
        if (ok) {
            for (int kk = lane; kk < TOK; kk += 32) {
                float p = expf(scw[kk] - mx);
                scw[kk] = p;
                sum += p;
            }
        }
#pragma unroll
        for (int o = 16; o > 0; o >>= 1) sum += __shfl_xor_sync(0xffffffffu, sum, o);
        float inv = 1.f / sum;
        __syncwarp();
        if (ok) {
            float ax = 0.f, ay = 0.f;
            for (int kk = 0; kk < TOK; kk++) {
                float p = scw[kk];
                float2 vv = __half22float2(vs2[kk * ATT_PAD + lane]);
                ax += p * vv.x; ay += p * vv.y;
            }
            ax *= inv; ay *= inv;
            size_t o0 = ((size_t)(b * TOK + nq)) * KP_D + h * DHD + lane * 2;
            __half h0 = __float2half(ax), h1 = __float2half(ay);
            a16[o0]             = h0;
            a16[o0 + 1]         = h1;
            a16[o0 + DIM]       = __float2half(ax - __half2float(h0));
            a16[o0 + DIM + 1]   = __float2half(ay - __half2float(h1));
            a16[o0 + 2 * DIM]   = h0;
            a16[o0 + 2 * DIM + 1] = h1;
        }
        __syncwarp();
    }
}

// fp32 SGEMM for the tiny head (M=32)
__global__ __launch_bounds__(256) void sgemm(
    const float* __restrict__ A, int lda,
    const float* __restrict__ W, const float* __restrict__ bias,
    float* __restrict__ C, int ldc, int M, int N, int K, int act)
{
    __shared__ float As[16][128];
    __shared__ float Bs[16][64];
    int tid = threadIdx.x;
    int tx = tid & 15, ty = tid >> 4;
    int row0 = blockIdx.y * 128;
    int col0 = blockIdx.x * 64;
    float acc[8][4];
#pragma unroll
    for (int i = 0; i < 8; i++)
#pragma unroll
        for (int j = 0; j < 4; j++) acc[i][j] = 0.f;
    for (int k0 = 0; k0 < K; k0 += 16) {
#pragma unroll
        for (int i = 0; i < 2; i++) {
            int idx = tid + i * 256;
            int r = idx >> 2, c = (idx & 3) << 2;
            int gr = row0 + r;
            float4 v = make_float4(0.f, 0.f, 0.f, 0.f);
            if (gr < M) v = *(const float4*)(A + (size_t)gr * lda + k0 + c);
            As[c + 0][r] = v.x; As[c + 1][r] = v.y; As[c + 2][r] = v.z; As[c + 3][r] = v.w;
        }
        {
            int n = tid >> 2, c = (tid & 3) << 2;
            int gn = col0 + n;
            float4 v = make_float4(0.f, 0.f, 0.f, 0.f);
            if (gn < N) v = *(const float4*)(W + (size_t)gn * K + k0 + c);
            Bs[c + 0][n] = v.x; Bs[c + 1][n] = v.y; Bs[c + 2][n] = v.z; Bs[c + 3][n] = v.w;
        }
        __syncthreads();
#pragma unroll
        for (int kk = 0; kk < 16; kk++) {
            float4 a0 = *(const float4*)&As[kk][ty * 8];
            float4 a1 = *(const float4*)&As[kk][ty * 8 + 4];
            float4 bb = *(const float4*)&Bs[kk][tx * 4];
            float av[8] = {a0.x, a0.y, a0.z, a0.w, a1.x, a1.y, a1.z, a1.w};
            float bv[4] = {bb.x, bb.y, bb.z, bb.w};
#pragma unroll
            for (int i = 0; i < 8; i++)
#pragma unroll
                for (int j = 0; j < 4; j++) acc[i][j] += av[i] * bv[j];
        }
        __syncthreads();
    }
#pragma unroll
    for (int i = 0; i < 8; i++) {
        int gr = row0 + ty * 8 + i;
        if (gr >= M) continue;
#pragma unroll
        for (int j = 0; j < 4; j++) {
            int gn = col0 + tx * 4 + j;
            if (gn >= N) continue;
            float v = acc[i][j];
            if (bias) v += bias[gn];
            if (act == 2) v = tanhf(v);
            C[(size_t)gr * ldc + gn] = v;
        }
    }
}

extern "C" void kernel_launch(void* const* d_in, const int* in_sizes, int n_in,
                              void* d_out, int out_size)
{
    const float* img     = (const float*)d_in[0];
    const float* patch_w = (const float*)d_in[1];
    const float* patch_b = (const float*)d_in[2];
    const float* cls_tok = (const float*)d_in[3];
    const float* pos_emb = (const float*)d_in[4];
    const float* ln1_w   = (const float*)d_in[5];
    const float* ln1_b   = (const float*)d_in[6];
    const float* qkv_w   = (const float*)d_in[7];
    const float* qkv_b   = (const float*)d_in[8];
    const float* proj_w  = (const float*)d_in[9];
    const float* proj_b  = (const float*)d_in[10];
    const float* ln2_w   = (const float*)d_in[11];
    const float* ln2_b   = (const float*)d_in[12];
    const float* ff1_w   = (const float*)d_in[13];
    const float* ff1_b   = (const float*)d_in[14];
    const float* ff2_w   = (const float*)d_in[15];
    const float* ff2_b   = (const float*)d_in[16];
    const float* head1_w = (const float*)d_in[17];
    const float* head1_b = (const float*)d_in[18];
    const float* head2_w = (const float*)d_in[19];
    const float* head2_b = (const float*)d_in[20];
    float* out = (float*)d_out;

    float *x, *qkv, *q, *k, *v, *tok, *hh;
    __half *a16, *f16, *wp, *wq, *wpr, *wf1, *wf2;
    cudaGetSymbolAddress((void**)&x,   g_x);
    cudaGetSymbolAddress((void**)&qkv, g_qkv);
    cudaGetSymbolAddress((void**)&q,   g_q);
    cudaGetSymbolAddress((void**)&k,   g_kk);
    cudaGetSymbolAddress((void**)&v,   g_v);
    cudaGetSymbolAddress((void**)&tok, g_tok);
    cudaGetSymbolAddress((void**)&hh,  g_hh);
    cudaGetSymbolAddress((void**)&a16, g_a16);
    cudaGetSymbolAddress((void**)&f16, g_f16);
    cudaGetSymbolAddress((void**)&wp,  g_wp16);
    cudaGetSymbolAddress((void**)&wq,  g_wqkv16);
    cudaGetSymbolAddress((void**)&wpr, g_wpr16);
    cudaGetSymbolAddress((void**)&wf1, g_wf1_16);
    cudaGetSymbolAddress((void**)&wf2, g_wf2_16);

    cudaFuncSetAttribute(hgemm, cudaFuncAttributeMaxDynamicSharedMemorySize, HG_SMEM);
    cudaFuncSetAttribute(attn2, cudaFuncAttributeMaxDynamicSharedMemorySize, ATT2_SMEM);

    // weights -> split fp16
    {
        long t;
        t = (long)DIM * DIM;  convert_w<<<(unsigned)((t + 255) / 256), 256>>>(patch_w, wp,  DIM, t);
        t = 12L * QKVD * DIM; convert_w<<<(unsigned)((t + 255) / 256), 256>>>(qkv_w,   wq,  DIM, t);
        t = 12L * DIM * DIM;  convert_w<<<(unsigned)((t + 255) / 256), 256>>>(proj_w,  wpr, DIM, t);
        t = 12L * FFD * DIM;  convert_w<<<(unsigned)((t + 255) / 256), 256>>>(ff1_w,   wf1, DIM, t);
        t = 12L * DIM * FFD;  convert_w<<<(unsigned)((t + 255) / 256), 256>>>(ff2_w,   wf2, FFD, t);
    }

    // patch embed
    {
        int tot = PATCH_ROWS * DIM;
        im2col_split<<<(tot + 255) / 256, 256>>>(img, a16);
        hgemm<<<dim3(6, 49), 256, HG_SMEM>>>(a16, wp, KP_D, patch_b, (const float*)0,
                                             tok, (__half*)0, DIM, PATCH_ROWS, 0);
        int tot2 = ROWS * DIM;
        assemble_kernel<<<(tot2 + 255) / 256, 256>>>(tok, cls_tok, pos_emb, x);
    }

    const int NELEM = BATCH * HEADS * TOK * DHD;
    for (int l = 0; l < 12; l++) {
        ln_split<<<ROWS, 256>>>(x, ln1_w + (size_t)l * DIM, ln1_b + (size_t)l * DIM, a16);
        hgemm<<<dim3(18, 50), 256, HG_SMEM>>>(a16, wq + (size_t)l * QKVD * KP_D, KP_D,
                                              qkv_b + (size_t)l * QKVD, (const float*)0,
                                              qkv, (__half*)0, QKVD, ROWS, 0);
        reorder_qkv<<<(NELEM + 255) / 256, 256>>>(qkv, q, k, v);
        attn2<<<BATCH * HEADS, 256, ATT2_SMEM>>>(q, k, v, a16);
        hgemm<<<dim3(6, 50), 256, HG_SMEM>>>(a16, wpr + (size_t)l * DIM * KP_D, KP_D,
                                             proj_b + (size_t)l * DIM, x,
                                             x, (__half*)0, DIM, ROWS, 1);
        ln_split<<<ROWS, 256>>>(x, ln2_w + (size_t)l * DIM, ln2_b + (size_t)l * DIM, a16);
        hgemm<<<dim3(24, 50), 256, HG_SMEM>>>(a16, wf1 + (size_t)l * FFD * KP_D, KP_D,
                                              ff1_b + (size_t)l * FFD, (const float*)0,
                                              (float*)0, f16, FFD, ROWS, 2);
        hgemm<<<dim3(6, 50), 256, HG_SMEM>>>(f16, wf2 + (size_t)l * DIM * KP_F, KP_F,
                                             ff2_b + (size_t)l * DIM, x,
                                             x, (__half*)0, DIM, ROWS, 1);
    }

    // head (fp32, tiny M)
    sgemm<<<dim3(48, 1), 256>>>(x, TOK * DIM, head1_w, head1_b, hh, FFD, BATCH, FFD, DIM, 2);
    sgemm<<<dim3(16, 1), 256>>>(hh, FFD, head2_w, head2_b, out, NCLSD, BATCH, NCLSD, FFD, 0);
}

// round 6
// speedup vs baseline: 3.3296x; 1.0579x over previous
#include <cuda_runtime.h>
#include <cuda_fp16.h>
#include <math.h>
#include <stdint.h>

#define BATCH 32
#define TOK 197
#define ROWS (BATCH*TOK)
#define MPAD 6400
#define DIM 768
#define HEADS 12
#define DHD 64
#define FFD 3072
#define QKVD 2304
#define NPATCH 196
#define PATCH_ROWS (BATCH*NPATCH)
#define NCLSD 1000
#define KP2_D (2*DIM)
#define KP2_F (2*FFD)

__device__ float  g_x   [ROWS*DIM];
__device__ float  g_qkv [ROWS*QKVD];
__device__ float  g_q   [BATCH*HEADS*TOK*DHD];
__device__ float  g_kk  [BATCH*HEADS*TOK*DHD];
__device__ float  g_v   [BATCH*HEADS*TOK*DHD];
__device__ float  g_tok [PATCH_ROWS*DIM];
__device__ float  g_hh  [BATCH*FFD];
__device__ __align__(128) __half g_a16 [MPAD*KP2_D];
__device__ __align__(128) __half g_f16 [(size_t)MPAD*KP2_F];
__device__ __align__(128) __half g_wp16  [DIM*KP2_D];
__device__ __align__(128) __half g_wqkv16[(size_t)12*QKVD*KP2_D];
__device__ __align__(128) __half g_wpr16 [(size_t)12*DIM*KP2_D];
__device__ __align__(128) __half g_wf1_16[(size_t)12*FFD*KP2_D];
__device__ __align__(128) __half g_wf2_16[(size_t)12*DIM*KP2_F];

__device__ __forceinline__ uint32_t smem_u32(const void* p) {
    uint32_t a;
    asm("{ .reg .u64 t; cvta.to.shared.u64 t, %1; cvt.u32.u64 %0, t; }" : "=r"(a) : "l"(p));
    return a;
}
__device__ __forceinline__ void cp_async16(uint32_t s, const void* g) {
    asm volatile("cp.async.cg.shared.global [%0], [%1], 16;\n" :: "r"(s), "l"(g));
}
#define CP_COMMIT() asm volatile("cp.async.commit_group;\n" ::: "memory")
#define CP_WAIT(n)  asm volatile("cp.async.wait_group %0;\n" :: "n"(n) : "memory")

__device__ __forceinline__ void ldsm_x4(uint32_t& r0, uint32_t& r1, uint32_t& r2, uint32_t& r3,
                                        uint32_t addr) {
    asm volatile("ldmatrix.sync.aligned.m8n8.x4.shared.b16 {%0,%1,%2,%3}, [%4];"
                 : "=r"(r0), "=r"(r1), "=r"(r2), "=r"(r3) : "r"(addr));
}
__device__ __forceinline__ void mma16816(float* c, const uint32_t* a, const uint32_t* b) {
    asm volatile("mma.sync.aligned.m16n8k16.row.col.f32.f16.f16.f32 "
        "{%0,%1,%2,%3}, {%4,%5,%6,%7}, {%8,%9}, {%0,%1,%2,%3};"
        : "+f"(c[0]), "+f"(c[1]), "+f"(c[2]), "+f"(c[3])
        : "r"(a[0]), "r"(a[1]), "r"(a[2]), "r"(a[3]), "r"(b[0]), "r"(b[1]));
}
__device__ __forceinline__ float gelu_f(float v) {
    return 0.5f * v * (1.0f + erff(v * 0.70710678118654752f));
}

// ===== split-fp16 HMMA GEMM v2: [hi|lo] operands, 3 products per K-chunk =====
// Tile 128x128, Kchunk=32, stage = {Ah,Al,Bh,Bl} 4x8KB = 32KB, 3 stages, 2 CTA/SM.
#define STAGE3 32768
#define HG_SMEM (3*STAGE3)

__global__ __launch_bounds__(256, 2) void hgemm(
    const __half* __restrict__ A, const __half* __restrict__ B, int K,  // original K
    const float* __restrict__ bias, const float* __restrict__ res,
    float* __restrict__ outF, __half* __restrict__ out16,
    int ldc, int M, int mode)
{
    extern __shared__ char smraw[];
    uint32_t smb = smem_u32(smraw);
    int tid = threadIdx.x;
    int lane = tid & 31, wid = tid >> 5;
    int warp_m = wid & 1, warp_n = wid >> 1;
    int row0 = blockIdx.y * 128, col0 = blockIdx.x * 128;

    int a_row0 = (tid + 0)   >> 2, a_c0 = (tid + 0)   & 3;
    int a_row1 = (tid + 256) >> 2, a_c1 = (tid + 256) & 3;
    uint32_t a_s0 = a_row0 * 64 + ((a_c0 ^ ((a_row0 >> 1) & 3)) << 4);
    uint32_t a_s1 = a_row1 * 64 + ((a_c1 ^ ((a_row1 >> 1) & 3)) << 4);

    int g = lane >> 3, l = lane & 7;
    uint32_t a_r64[4], a_rx[4];
#pragma unroll
    for (int mi = 0; mi < 4; mi++) {
        int r = warp_m * 64 + mi * 16 + (g & 1) * 8 + l;
        a_r64[mi] = r * 64; a_rx[mi] = (r >> 1) & 3;
    }
    uint32_t b_r64[2], b_rx[2];
#pragma unroll
    for (int j2 = 0; j2 < 2; j2++) {
        int r = warp_n * 32 + j2 * 16 + (g >> 1) * 8 + l;
        b_r64[j2] = r * 64; b_rx[j2] = (r >> 1) & 3;
    }

    float acc[4][4][4];
#pragma unroll
    for (int mi = 0; mi < 4; mi++)
#pragma unroll
        for (int nj = 0; nj < 4; nj++)
#pragma unroll
            for (int q = 0; q < 4; q++) acc[mi][nj][q] = 0.f;

    const int KT = K >> 5;
    const size_t str = (size_t)(2 * K);

#define LOAD_ST(s, kb) do { \
    uint32_t sa = smb + (uint32_t)(s) * STAGE3; \
    const __half* gAh = A + (size_t)(row0) * str + (size_t)(kb) * 32; \
    cp_async16(sa + a_s0, gAh + (size_t)a_row0 * str + a_c0 * 8); \
    cp_async16(sa + a_s1, gAh + (size_t)a_row1 * str + a_c1 * 8); \
    cp_async16(sa + 8192u + a_s0, gAh + (size_t)a_row0 * str + K + a_c0 * 8); \
    cp_async16(sa + 8192u + a_s1, gAh + (size_t)a_row1 * str + K + a_c1 * 8); \
    const __half* gBh = B + (size_t)(col0) * str + (size_t)(kb) * 32; \
    cp_async16(sa + 16384u + a_s0, gBh + (size_t)a_row0 * str + a_c0 * 8); \
    cp_async16(sa + 16384u + a_s1, gBh + (size_t)a_row1 * str + a_c1 * 8); \
    cp_async16(sa + 24576u + a_s0, gBh + (size_t)a_row0 * str + K + a_c0 * 8); \
    cp_async16(sa + 24576u + a_s1, gBh + (size_t)a_row1 * str + K + a_c1 * 8); \
} while (0)

    LOAD_ST(0, 0); CP_COMMIT();
    LOAD_ST(1, 1); CP_COMMIT();

    int cur = 0;
    for (int i = 0; i < KT; i++) {
        CP_WAIT(1);
        __syncthreads();
        if (i + 2 < KT) {
            int sp = cur + 2; if (sp >= 3) sp -= 3;
            LOAD_ST(sp, i + 2);
        }
        CP_COMMIT();

        uint32_t ah_b = smb + (uint32_t)cur * STAGE3;
        uint32_t al_b = ah_b + 8192u;
        uint32_t bh_b = ah_b + 16384u;
        uint32_t bl_b = ah_b + 24576u;
#pragma unroll
        for (int ks = 0; ks < 2; ks++) {
            uint32_t cha = (uint32_t)(ks * 2 + (g >> 1));
            uint32_t chb = (uint32_t)(ks * 2 + (g & 1));
            uint32_t afh[4][4], afl[4][4], bf[4][2];
#pragma unroll
            for (int mi = 0; mi < 4; mi++)
                ldsm_x4(afh[mi][0], afh[mi][1], afh[mi][2], afh[mi][3],
                        ah_b + a_r64[mi] + ((cha ^ a_rx[mi]) << 4));
#pragma unroll
            for (int j2 = 0; j2 < 2; j2++)
                ldsm_x4(bf[j2 * 2][0], bf[j2 * 2][1], bf[j2 * 2 + 1][0], bf[j2 * 2 + 1][1],
                        bh_b + b_r64[j2] + ((chb ^ b_rx[j2]) << 4));
#pragma unroll
            for (int mi = 0; mi < 4; mi++)
#pragma unroll
                for (int nj = 0; nj < 4; nj++)
                    mma16816(acc[mi][nj], afh[mi], bf[nj]);
#pragma unroll
            for (int mi = 0; mi < 4; mi++)
                ldsm_x4(afl[mi][0], afl[mi][1], afl[mi][2], afl[mi][3],
                        al_b + a_r64[mi] + ((cha ^ a_rx[mi]) << 4));
#pragma unroll
            for (int mi = 0; mi < 4; mi++)
#pragma unroll
                for (int nj = 0; nj < 4; nj++)
                    mma16816(acc[mi][nj], afl[mi], bf[nj]);
#pragma unroll
            for (int j2 = 0; j2 < 2; j2++)
                ldsm_x4(bf[j2 * 2][0], bf[j2 * 2][1], bf[j2 * 2 + 1][0], bf[j2 * 2 + 1][1],
                        bl_b + b_r64[j2] + ((chb ^ b_rx[j2]) << 4));
#pragma unroll
            for (int mi = 0; mi < 4; mi++)
#pragma unroll
                for (int nj = 0; nj < 4; nj++)
                    mma16816(acc[mi][nj], afh[mi], bf[nj]);
        }
        cur++; if (cur >= 3) cur = 0;
    }

    int qrow = lane >> 2, qcol = (lane & 3) * 2;
#pragma unroll
    for (int mi = 0; mi < 4; mi++) {
        int rbase = row0 + warp_m * 64 + mi * 16 + qrow;
#pragma unroll
        for (int half = 0; half < 2; half++) {
            int r = rbase + half * 8;
            if (r >= M) continue;
#pragma unroll
            for (int nj = 0; nj < 4; nj++) {
                int c = col0 + warp_n * 32 + nj * 8 + qcol;
                float v0 = acc[mi][nj][half * 2 + 0] + __ldg(bias + c);
                float v1 = acc[mi][nj][half * 2 + 1] + __ldg(bias + c + 1);
                if (mode == 2) {
                    float g0 = gelu_f(v0), g1 = gelu_f(v1);
                    __half h0 = __float2half(g0), h1 = __float2half(g1);
                    __half l0 = __float2half(g0 - __half2float(h0));
                    __half l1 = __float2half(g1 - __half2float(h1));
                    __half* o = out16 + (size_t)r * (2 * ldc) + c;
                    *(__half2*)(o)       = __halves2half2(h0, h1);
                    *(__half2*)(o + ldc) = __halves2half2(l0, l1);
                } else {
                    float* o = outF + (size_t)r * ldc + c;
                    if (mode == 1) {
                        const float* rr = res + (size_t)r * ldc + c;
                        v0 += rr[0]; v1 += rr[1];
                    }
                    *(float2*)o = make_float2(v0, v1);
                }
            }
        }
    }
}

// ===== helpers (all [hi|lo] 2K-wide layout) =====
__global__ void convert_w(const float* __restrict__ W, __half* __restrict__ W16,
                          int K, long total)
{
    long idx = (long)blockIdx.x * blockDim.x + threadIdx.x;
    if (idx >= total) return;
    long row = idx / K; int k = (int)(idx - row * K);
    float v = W[idx];
    __half hi = __float2half(v);
    __half* dst = W16 + row * (2L * K);
    dst[k] = hi; dst[K + k] = __float2half(v - __half2float(hi));
}

__global__ __launch_bounds__(256) void ln_split(
    const float* __restrict__ x, const float* __restrict__ w,
    const float* __restrict__ b, __half* __restrict__ y16)
{
    int row = blockIdx.x;
    const float* xr = x + (size_t)row * DIM;
    __shared__ float red[256];
    int tid = threadIdx.x;
    float s = 0.f;
    for (int i = tid; i < DIM; i += 256) s += xr[i];
    red[tid] = s; __syncthreads();
    for (int o = 128; o > 0; o >>= 1) { if (tid < o) red[tid] += red[tid + o]; __syncthreads(); }
    float mean = red[0] * (1.0f / DIM);
    __syncthreads();
    float s2 = 0.f;
    for (int i = tid; i < DIM; i += 256) { float d = xr[i] - mean; s2 += d * d; }
    red[tid] = s2; __syncthreads();
    for (int o = 128; o > 0; o >>= 1) { if (tid < o) red[tid] += red[tid + o]; __syncthreads(); }
    float inv = rsqrtf(red[0] * (1.0f / DIM) + 1e-5f);
    __half* yr = y16 + (size_t)row * KP2_D;
    for (int i = tid; i < DIM; i += 256) {
        float v = (xr[i] - mean) * inv * w[i] + b[i];
        __half hi = __float2half(v);
        yr[i] = hi;
        yr[DIM + i] = __float2half(v - __half2float(hi));
    }
}

__global__ void im2col_split(const float* __restrict__ img, __half* __restrict__ a16)
{
    int idx = blockIdx.x * blockDim.x + threadIdx.x;
    if (idx >= PATCH_ROWS * DIM) return;
    int e = idx % DIM;
    int m = idx / DIM;
    int b = m / NPATCH, p = m % NPATCH;
    int gr = p / 14, gc = p % 14;
    int c = e % 3;
    int pp = e / 3;
    int pr = pp / 16, pc = pp % 16;
    float v = img[(((size_t)b * 3 + c) * 224 + gr * 16 + pr) * 224 + gc * 16 + pc];
    __half hi = __float2half(v);
    __half* dst = a16 + (size_t)m * KP2_D;
    dst[e] = hi;
    dst[DIM + e] = __float2half(v - __half2float(hi));
}

__global__ void assemble_kernel(const float* __restrict__ tokens,
                                const float* __restrict__ cls,
                                const float* __restrict__ pos,
                                float* __restrict__ x)
{
    int idx = blockIdx.x * blockDim.x + threadIdx.x;
    if (idx >= ROWS * DIM) return;
    int d = idx % DIM;
    int r = idx / DIM;
    int b = r / TOK, n = r % TOK;
    float v = (n == 0) ? cls[d] : tokens[((size_t)b * NPATCH + (n - 1)) * DIM + d];
    x[idx] = v + pos[(size_t)n * DIM + d];
}

__global__ void reorder_qkv(const float* __restrict__ qkv,
                            float* __restrict__ Q, float* __restrict__ K, float* __restrict__ V)
{
    int idx = blockIdx.x * blockDim.x + threadIdx.x;
    const int total = BATCH * HEADS * TOK * DHD;
    if (idx >= total) return;
    int d = idx & 63;
    int n = (idx >> 6) % TOK;
    int h = (idx >> 6) / TOK % HEADS;
    int b = idx / (64 * TOK * HEADS);
    const float* src = qkv + ((size_t)(b * TOK + n)) * QKVD + h * 192 + d * 3;
    Q[idx] = src[0]; K[idx] = src[1]; V[idx] = src[2];
}

// ===== attention: warp-per-query, fp16 K/V in smem, shuffle softmax =====
#define ATT_PAD 33
#define ATT2_SMEM ((2*TOK*ATT_PAD + 8*ATT_PAD) * 4 + 8*200*4)

__global__ __launch_bounds__(256) void attn2(
    const float* __restrict__ Q, const float* __restrict__ K,
    const float* __restrict__ V, __half* __restrict__ a16)
{
    extern __shared__ char smraw[];
    __half2* ks2 = (__half2*)smraw;
    __half2* vs2 = ks2 + TOK * ATT_PAD;
    __half2* qs2 = vs2 + TOK * ATT_PAD;
    float*   sc  = (float*)(qs2 + 8 * ATT_PAD);

    int bh = blockIdx.x;
    int b = bh / HEADS, h = bh % HEADS;
    int tid = threadIdx.x, lane = tid & 31, w = tid >> 5;
    const float2* Qb = (const float2*)(Q + (size_t)bh * TOK * DHD);
    const float2* Kb = (const float2*)(K + (size_t)bh * TOK * DHD);
    const float2* Vb = (const float2*)(V + (size_t)bh * TOK * DHD);

    for (int i = tid; i < TOK * 32; i += 256) {
        int n = i >> 5, d2 = i & 31;
        float2 kv = Kb[i];
        float2 vv = Vb[i];
        ks2[n * ATT_PAD + d2] = __floats2half2_rn(kv.x, kv.y);
        vs2[n * ATT_PAD + d2] = __floats2half2_rn(vv.x, vv.y);
    }
    __syncthreads();

    float* scw = sc + w * 200;
    for (int base = 0; base < TOK; base += 8) {
        int nq = base + w;
        bool ok = (nq < TOK);
        if (ok) {
            float2 qv = Qb[(size_t)nq * 32 + lane];
            qs2[w * ATT_PAD + lane] = __floats2half2_rn(qv.x, qv.y);
        }
        __syncwarp();
        float mx = -1e30f;
        if (ok) {
            for (int kk = lane; kk < TOK; kk += 32) {
                float s = 0.f;
#pragma unroll
                for (int d2 = 0; d2 < 32; d2++) {
                    float2 kv = __half22float2(ks2[kk * ATT_PAD + d2]);
                    float2 qv = __half22float2(qs2[w * ATT_PAD + d2]);
                    s += kv.x * qv.x + kv.y * qv.y;
                }
                s *= 0.125f;
                scw[kk] = s;
                mx = fmaxf(mx, s);
            }
        }
#pragma unroll
        for (int o = 16; o > 0; o >>= 1) mx = fmaxf(mx, __shfl_xor_sync(0xffffffffu, mx, o));
        float sum = 0.f;
        if (ok) {
            for (int kk = lane; kk < TOK; kk += 32) {
                float p = expf(scw[kk] - mx);
                scw[kk] = p;
                sum += p;
            }
        }
#pragma unroll
        for (int o = 16; o > 0; o >>= 1) sum += __shfl_xor_sync(0xffffffffu, sum, o);
        float inv = 1.f / sum;
        __syncwarp();
        if (ok) {
            float ax = 0.f, ay = 0.f;
            for (int kk = 0; kk < TOK; kk++) {
                float p = scw[kk];
                float2 vv = __half22float2(vs2[kk * ATT_PAD + lane]);
                ax += p * vv.x; ay += p * vv.y;
            }
            ax *= inv; ay *= inv;
            size_t o0 = ((size_t)(b * TOK + nq)) * KP2_D + h * DHD + lane * 2;
            __half h0 = __float2half(ax), h1 = __float2half(ay);
            a16[o0]           = h0;
            a16[o0 + 1]       = h1;
            a16[o0 + DIM]     = __float2half(ax - __half2float(h0));
            a16[o0 + DIM + 1] = __float2half(ay - __half2float(h1));
        }
        __syncwarp();
    }
}

// fp32 SGEMM for the tiny head (M=32)
__global__ __launch_bounds__(256) void sgemm(
    const float* __restrict__ A, int lda,
    const float* __restrict__ W, const float* __restrict__ bias,
    float* __restrict__ C, int ldc, int M, int N, int K, int act)
{
    __shared__ float As[16][128];
    __shared__ float Bs[16][64];
    int tid = threadIdx.x;
    int tx = tid & 15, ty = tid >> 4;
    int row0 = blockIdx.y * 128;
    int col0 = blockIdx.x * 64;
    float acc[8][4];
#pragma unroll
    for (int i = 0; i < 8; i++)
#pragma unroll
        for (int j = 0; j < 4; j++) acc[i][j] = 0.f;
    for (int k0 = 0; k0 < K; k0 += 16) {
#pragma unroll
        for (int i = 0; i < 2; i++) {
            int idx = tid + i * 256;
            int r = idx >> 2, c = (idx & 3) << 2;
            int gr = row0 + r;
            float4 v = make_float4(0.f, 0.f, 0.f, 0.f);
            if (gr < M) v = *(const float4*)(A + (size_t)gr * lda + k0 + c);
            As[c + 0][r] = v.x; As[c + 1][r] = v.y; As[c + 2][r] = v.z; As[c + 3][r] = v.w;
        }
        {
            int n = tid >> 2, c = (tid & 3) << 2;
            int gn = col0 + n;
            float4 v = make_float4(0.f, 0.f, 0.f, 0.f);
            if (gn < N) v = *(const float4*)(W + (size_t)gn * K + k0 + c);
            Bs[c + 0][n] = v.x; Bs[c + 1][n] = v.y; Bs[c + 2][n] = v.z; Bs[c + 3][n] = v.w;
        }
        __syncthreads();
#pragma unroll
        for (int kk = 0; kk < 16; kk++) {
            float4 a0 = *(const float4*)&As[kk][ty * 8];
            float4 a1 = *(const float4*)&As[kk][ty * 8 + 4];
            float4 bb = *(const float4*)&Bs[kk][tx * 4];
            float av[8] = {a0.x, a0.y, a0.z, a0.w, a1.x, a1.y, a1.z, a1.w};
            float bv[4] = {bb.x, bb.y, bb.z, bb.w};
#pragma unroll
            for (int i = 0; i < 8; i++)
#pragma unroll
                for (int j = 0; j < 4; j++) acc[i][j] += av[i] * bv[j];
        }
        __syncthreads();
    }
#pragma unroll
    for (int i = 0; i < 8; i++) {
        int gr = row0 + ty * 8 + i;
        if (gr >= M) continue;
#pragma unroll
        for (int j = 0; j < 4; j++) {
            int gn = col0 + tx * 4 + j;
            if (gn >= N) continue;
            float v = acc[i][j];
            if (bias) v += bias[gn];
            if (act == 2) v = tanhf(v);
            C[(size_t)gr * ldc + gn] = v;
        }
    }
}

extern "C" void kernel_launch(void* const* d_in, const int* in_sizes, int n_in,
                              void* d_out, int out_size)
{
    const float* img     = (const float*)d_in[0];
    const float* patch_w = (const float*)d_in[1];
    const float* patch_b = (const float*)d_in[2];
    const float* cls_tok = (const float*)d_in[3];
    const float* pos_emb = (const float*)d_in[4];
    const float* ln1_w   = (const float*)d_in[5];
    const float* ln1_b   = (const float*)d_in[6];
    const float* qkv_w   = (const float*)d_in[7];
    const float* qkv_b   = (const float*)d_in[8];
    const float* proj_w  = (const float*)d_in[9];
    const float* proj_b  = (const float*)d_in[10];
    const float* ln2_w   = (const float*)d_in[11];
    const float* ln2_b   = (const float*)d_in[12];
    const float* ff1_w   = (const float*)d_in[13];
    const float* ff1_b   = (const float*)d_in[14];
    const float* ff2_w   = (const float*)d_in[15];
    const float* ff2_b   = (const float*)d_in[16];
    const float* head1_w = (const float*)d_in[17];
    const float* head1_b = (const float*)d_in[18];
    const float* head2_w = (const float*)d_in[19];
    const float* head2_b = (const float*)d_in[20];
    float* out = (float*)d_out;

    float *x, *qkv, *q, *k, *v, *tok, *hh;
    __half *a16, *f16, *wp, *wq, *wpr, *wf1, *wf2;
    cudaGetSymbolAddress((void**)&x,   g_x);
    cudaGetSymbolAddress((void**)&qkv, g_qkv);
    cudaGetSymbolAddress((void**)&q,   g_q);
    cudaGetSymbolAddress((void**)&k,   g_kk);
    cudaGetSymbolAddress((void**)&v,   g_v);
    cudaGetSymbolAddress((void**)&tok, g_tok);
    cudaGetSymbolAddress((void**)&hh,  g_hh);
    cudaGetSymbolAddress((void**)&a16, g_a16);
    cudaGetSymbolAddress((void**)&f16, g_f16);
    cudaGetSymbolAddress((void**)&wp,  g_wp16);
    cudaGetSymbolAddress((void**)&wq,  g_wqkv16);
    cudaGetSymbolAddress((void**)&wpr, g_wpr16);
    cudaGetSymbolAddress((void**)&wf1, g_wf1_16);
    cudaGetSymbolAddress((void**)&wf2, g_wf2_16);

    cudaFuncSetAttribute(hgemm, cudaFuncAttributeMaxDynamicSharedMemorySize, HG_SMEM);
    cudaFuncSetAttribute(attn2, cudaFuncAttributeMaxDynamicSharedMemorySize, ATT2_SMEM);

    // weights -> split fp16 [hi|lo]
    {
        long t;
        t = (long)DIM * DIM;  convert_w<<<(unsigned)((t + 255) / 256), 256>>>(patch_w, wp,  DIM, t);
        t = 12L * QKVD * DIM; convert_w<<<(unsigned)((t + 255) / 256), 256>>>(qkv_w,   wq,  DIM, t);
        t = 12L * DIM * DIM;  convert_w<<<(unsigned)((t + 255) / 256), 256>>>(proj_w,  wpr, DIM, t);
        t = 12L * FFD * DIM;  convert_w<<<(unsigned)((t + 255) / 256), 256>>>(ff1_w,   wf1, DIM, t);
        t = 12L * DIM * FFD;  convert_w<<<(unsigned)((t + 255) / 256), 256>>>(ff2_w,   wf2, FFD, t);
    }

    // patch embed
    {
        int tot = PATCH_ROWS * DIM;
        im2col_split<<<(tot + 255) / 256, 256>>>(img, a16);
        hgemm<<<dim3(6, 49), 256, HG_SMEM>>>(a16, wp, DIM, patch_b, (const float*)0,
                                             tok, (__half*)0, DIM, PATCH_ROWS, 0);
        int tot2 = ROWS * DIM;
        assemble_kernel<<<(tot2 + 255) / 256, 256>>>(tok, cls_tok, pos_emb, x);
    }

    const int NELEM = BATCH * HEADS * TOK * DHD;
    for (int l = 0; l < 12; l++) {
        ln_split<<<ROWS, 256>>>(x, ln1_w + (size_t)l * DIM, ln1_b + (size_t)l * DIM, a16);
        hgemm<<<dim3(18, 50), 256, HG_SMEM>>>(a16, wq + (size_t)l * QKVD * KP2_D, DIM,
                                              qkv_b + (size_t)l * QKVD, (const float*)0,
                                              qkv, (__half*)0, QKVD, ROWS, 0);
        reorder_qkv<<<(NELEM + 255) / 256, 256>>>(qkv, q, k, v);
        attn2<<<BATCH * HEADS, 256, ATT2_SMEM>>>(q, k, v, a16);
        hgemm<<<dim3(6, 50), 256, HG_SMEM>>>(a16, wpr + (size_t)l * DIM * KP2_D, DIM,
                                             proj_b + (size_t)l * DIM, x,
                                             x, (__half*)0, DIM, ROWS, 1);
        ln_split<<<ROWS, 256>>>(x, ln2_w + (size_t)l * DIM, ln2_b + (size_t)l * DIM, a16);
        hgemm<<<dim3(24, 50), 256, HG_SMEM>>>(a16, wf1 + (size_t)l * FFD * KP2_D, DIM,
                                              ff1_b + (size_t)l * FFD, (const float*)0,
                                              (float*)0, f16, FFD, ROWS, 2);
        hgemm<<<dim3(6, 50), 256, HG_SMEM>>>(f16, wf2 + (size_t)l * DIM * KP2_F, FFD,
                                             ff2_b + (size_t)l * DIM, x,
                                             x, (__half*)0, DIM, ROWS, 1);
    }

    // head (fp32, tiny M)
    sgemm<<<dim3(48, 1), 256>>>(x, TOK * DIM, head1_w, head1_b, hh, FFD, BATCH, FFD, DIM, 2);
    sgemm<<<dim3(16, 1), 256>>>(hh, FFD, head2_w, head2_b, out, NCLSD, BATCH, NCLSD, FFD, 0);
}

// round 7
// speedup vs baseline: 3.8962x; 1.1702x over previous
#include <cuda_runtime.h>
#include <cuda_fp16.h>
#include <math.h>
#include <stdint.h>

#define BATCH 32
#define TOK 197
#define ROWS (BATCH*TOK)
#define MPAD 6400
#define DIM 768
#define HEADS 12
#define DHD 64
#define FFD 3072
#define QKVD 2304
#define NPATCH 196
#define PATCH_ROWS (BATCH*NPATCH)
#define NCLSD 1000
#define KP2_D (2*DIM)
#define KP2_F (2*FFD)

__device__ float  g_x   [ROWS*DIM];
__device__ float  g_q   [BATCH*HEADS*TOK*DHD];
__device__ float  g_kk  [BATCH*HEADS*TOK*DHD];
__device__ float  g_v   [BATCH*HEADS*TOK*DHD];
__device__ float  g_tok [PATCH_ROWS*DIM];
__device__ float  g_hh  [BATCH*FFD];
__device__ __align__(128) __half g_a16 [MPAD*KP2_D];
__device__ __align__(128) __half g_f16 [(size_t)MPAD*KP2_F];
__device__ __align__(128) __half g_wp16  [DIM*DIM];
__device__ __align__(128) __half g_wqkv16[(size_t)12*QKVD*DIM];
__device__ __align__(128) __half g_wpr16 [(size_t)12*DIM*DIM];
__device__ __align__(128) __half g_wf1_16[(size_t)12*FFD*DIM];
__device__ __align__(128) __half g_wf2_16[(size_t)12*DIM*FFD];

__device__ __forceinline__ uint32_t smem_u32(const void* p) {
    uint32_t a;
    asm("{ .reg .u64 t; cvta.to.shared.u64 t, %1; cvt.u32.u64 %0, t; }" : "=r"(a) : "l"(p));
    return a;
}
__device__ __forceinline__ void cp_async16(uint32_t s, const void* g) {
    asm volatile("cp.async.cg.shared.global [%0], [%1], 16;\n" :: "r"(s), "l"(g));
}
#define CP_COMMIT() asm volatile("cp.async.commit_group;\n" ::: "memory")
#define CP_WAIT(n)  asm volatile("cp.async.wait_group %0;\n" :: "n"(n) : "memory")

__device__ __forceinline__ void ldsm_x4(uint32_t& r0, uint32_t& r1, uint32_t& r2, uint32_t& r3,
                                        uint32_t addr) {
    asm volatile("ldmatrix.sync.aligned.m8n8.x4.shared.b16 {%0,%1,%2,%3}, [%4];"
                 : "=r"(r0), "=r"(r1), "=r"(r2), "=r"(r3) : "r"(addr));
}
__device__ __forceinline__ void mma16816(float* c, const uint32_t* a, const uint32_t* b) {
    asm volatile("mma.sync.aligned.m16n8k16.row.col.f32.f16.f16.f32 "
        "{%0,%1,%2,%3}, {%4,%5,%6,%7}, {%8,%9}, {%0,%1,%2,%3};"
        : "+f"(c[0]), "+f"(c[1]), "+f"(c[2]), "+f"(c[3])
        : "r"(a[0]), "r"(a[1]), "r"(a[2]), "r"(a[3]), "r"(b[0]), "r"(b[1]));
}
__device__ __forceinline__ float gelu_f(float v) {
    return 0.5f * v * (1.0f + erff(v * 0.70710678118654752f));
}

// ===== split-fp16 HMMA GEMM v3: A=[hi|lo] (2K wide), B=plain fp16, 2 products =====
// Tile 128x128, Kchunk=32, stage = {Ah,Al,Bh} 3x8KB = 24KB, 3 stages, 2 CTA/SM.
// mode 0: fp32 bias; 1: fp32 bias+res; 2: gelu -> [hi|lo]; 3: qkv scatter to Q/K/V
#define STAGE3 24576
#define HG_SMEM (3*STAGE3)

__global__ __launch_bounds__(256, 2) void hgemm(
    const __half* __restrict__ A, const __half* __restrict__ B, int K,
    const float* __restrict__ bias, const float* __restrict__ res,
    float* __restrict__ outF, __half* __restrict__ out16,
    float* __restrict__ gq, float* __restrict__ gk, float* __restrict__ gv,
    int ldc, int M, int mode)
{
    extern __shared__ char smraw[];
    uint32_t smb = smem_u32(smraw);
    int tid = threadIdx.x;
    int lane = tid & 31, wid = tid >> 5;
    int warp_m = wid & 1, warp_n = wid >> 1;
    int row0 = blockIdx.y * 128, col0 = blockIdx.x * 128;

    int a_row0 = (tid + 0)   >> 2, a_c0 = (tid + 0)   & 3;
    int a_row1 = (tid + 256) >> 2, a_c1 = (tid + 256) & 3;
    uint32_t a_s0 = a_row0 * 64 + ((a_c0 ^ ((a_row0 >> 1) & 3)) << 4);
    uint32_t a_s1 = a_row1 * 64 + ((a_c1 ^ ((a_row1 >> 1) & 3)) << 4);

    int g = lane >> 3, l = lane & 7;
    uint32_t a_r64[4], a_rx[4];
#pragma unroll
    for (int mi = 0; mi < 4; mi++) {
        int r = warp_m * 64 + mi * 16 + (g & 1) * 8 + l;
        a_r64[mi] = r * 64; a_rx[mi] = (r >> 1) & 3;
    }
    uint32_t b_r64[2], b_rx[2];
#pragma unroll
    for (int j2 = 0; j2 < 2; j2++) {
        int r = warp_n * 32 + j2 * 16 + (g >> 1) * 8 + l;
        b_r64[j2] = r * 64; b_rx[j2] = (r >> 1) & 3;
    }

    float acc[4][4][4];
#pragma unroll
    for (int mi = 0; mi < 4; mi++)
#pragma unroll
        for (int nj = 0; nj < 4; nj++)
#pragma unroll
            for (int q = 0; q < 4; q++) acc[mi][nj][q] = 0.f;

    const int KT = K >> 5;
    const size_t strA = (size_t)(2 * K);
    const size_t strB = (size_t)K;

#define LOAD_ST(s, kb) do { \
    uint32_t sa = smb + (uint32_t)(s) * STAGE3; \
    const __half* gA = A + (size_t)(row0) * strA + (size_t)(kb) * 32; \
    cp_async16(sa + a_s0, gA + (size_t)a_row0 * strA + a_c0 * 8); \
    cp_async16(sa + a_s1, gA + (size_t)a_row1 * strA + a_c1 * 8); \
    cp_async16(sa + 8192u + a_s0, gA + (size_t)a_row0 * strA + K + a_c0 * 8); \
    cp_async16(sa + 8192u + a_s1, gA + (size_t)a_row1 * strA + K + a_c1 * 8); \
    const __half* gB = B + (size_t)(col0) * strB + (size_t)(kb) * 32; \
    cp_async16(sa + 16384u + a_s0, gB + (size_t)a_row0 * strB + a_c0 * 8); \
    cp_async16(sa + 16384u + a_s1, gB + (size_t)a_row1 * strB + a_c1 * 8); \
} while (0)

    LOAD_ST(0, 0); CP_COMMIT();
    LOAD_ST(1, 1); CP_COMMIT();

    int cur = 0;
    for (int i = 0; i < KT; i++) {
        CP_WAIT(1);
        __syncthreads();
        if (i + 2 < KT) {
            int sp = cur + 2; if (sp >= 3) sp -= 3;
            LOAD_ST(sp, i + 2);
        }
        CP_COMMIT();

        uint32_t ah_b = smb + (uint32_t)cur * STAGE3;
        uint32_t al_b = ah_b + 8192u;
        uint32_t bh_b = ah_b + 16384u;
#pragma unroll
        for (int ks = 0; ks < 2; ks++) {
            uint32_t cha = (uint32_t)(ks * 2 + (g >> 1));
            uint32_t chb = (uint32_t)(ks * 2 + (g & 1));
            uint32_t afh[4][4], afl[4][4], bf[4][2];
#pragma unroll
            for (int mi = 0; mi < 4; mi++)
                ldsm_x4(afh[mi][0], afh[mi][1], afh[mi][2], afh[mi][3],
                        ah_b + a_r64[mi] + ((cha ^ a_rx[mi]) << 4));
#pragma unroll
            for (int j2 = 0; j2 < 2; j2++)
                ldsm_x4(bf[j2 * 2][0], bf[j2 * 2][1], bf[j2 * 2 + 1][0], bf[j2 * 2 + 1][1],
                        bh_b + b_r64[j2] + ((chb ^ b_rx[j2]) << 4));
#pragma unroll
            for (int mi = 0; mi < 4; mi++)
#pragma unroll
                for (int nj = 0; nj < 4; nj++)
                    mma16816(acc[mi][nj], afh[mi], bf[nj]);
#pragma unroll
            for (int mi = 0; mi < 4; mi++)
                ldsm_x4(afl[mi][0], afl[mi][1], afl[mi][2], afl[mi][3],
                        al_b + a_r64[mi] + ((cha ^ a_rx[mi]) << 4));
#pragma unroll
            for (int mi = 0; mi < 4; mi++)
#pragma unroll
                for (int nj = 0; nj < 4; nj++)
                    mma16816(acc[mi][nj], afl[mi], bf[nj]);
        }
        cur++; if (cur >= 3) cur = 0;
    }

    int qrow = lane >> 2, qcol = (lane & 3) * 2;
#pragma unroll
    for (int mi = 0; mi < 4; mi++) {
        int rbase = row0 + warp_m * 64 + mi * 16 + qrow;
#pragma unroll
        for (int half = 0; half < 2; half++) {
            int r = rbase + half * 8;
            if (r >= M) continue;
            int rb = r / TOK, rn = r - rb * TOK;   // for mode 3
#pragma unroll
            for (int nj = 0; nj < 4; nj++) {
                int c = col0 + warp_n * 32 + nj * 8 + qcol;
                float v0 = acc[mi][nj][half * 2 + 0] + __ldg(bias + c);
                float v1 = acc[mi][nj][half * 2 + 1] + __ldg(bias + c + 1);
                if (mode == 2) {
                    float g0 = gelu_f(v0), g1 = gelu_f(v1);
                    __half h0 = __float2half(g0), h1 = __float2half(g1);
                    __half l0 = __float2half(g0 - __half2float(h0));
                    __half l1 = __float2half(g1 - __half2float(h1));
                    __half* o = out16 + (size_t)r * (2 * ldc) + c;
                    *(__half2*)(o)       = __halves2half2(h0, h1);
                    *(__half2*)(o + ldc) = __halves2half2(l0, l1);
                } else if (mode == 3) {
                    // scatter to Q/K/V: col n = h*192 + d*3 + s
#pragma unroll
                    for (int e = 0; e < 2; e++) {
                        int cc = c + e;
                        float vv = e ? v1 : v0;
                        int hh = cc / 192;
                        int t  = cc - hh * 192;
                        int dd = t / 3;
                        int ss = t - dd * 3;
                        float* dst = (ss == 0) ? gq : (ss == 1) ? gk : gv;
                        dst[(((size_t)(rb * HEADS + hh)) * TOK + rn) * DHD + dd] = vv;
                    }
                } else {
                    float* o = outF + (size_t)r * ldc + c;
                    if (mode == 1) {
                        const float* rr = res + (size_t)r * ldc + c;
                        v0 += rr[0]; v1 += rr[1];
                    }
                    *(float2*)o = make_float2(v0, v1);
                }
            }
        }
    }
}

// ===== helpers =====
__global__ void convert_w(const float* __restrict__ W, __half* __restrict__ W16, long total)
{
    long idx = (long)blockIdx.x * blockDim.x + threadIdx.x;
    if (idx >= total) return;
    W16[idx] = __float2half(W[idx]);
}

__global__ __launch_bounds__(256) void ln_split(
    const float* __restrict__ x, const float* __restrict__ w,
    const float* __restrict__ b, __half* __restrict__ y16)
{
    int row = blockIdx.x;
    const float* xr = x + (size_t)row * DIM;
    __shared__ float red[256];
    int tid = threadIdx.x;
    float s = 0.f;
    for (int i = tid; i < DIM; i += 256) s += xr[i];
    red[tid] = s; __syncthreads();
    for (int o = 128; o > 0; o >>= 1) { if (tid < o) red[tid] += red[tid + o]; __syncthreads(); }
    float mean = red[0] * (1.0f / DIM);
    __syncthreads();
    float s2 = 0.f;
    for (int i = tid; i < DIM; i += 256) { float d = xr[i] - mean; s2 += d * d; }
    red[tid] = s2; __syncthreads();
    for (int o = 128; o > 0; o >>= 1) { if (tid < o) red[tid] += red[tid + o]; __syncthreads(); }
    float inv = rsqrtf(red[0] * (1.0f / DIM) + 1e-5f);
    __half* yr = y16 + (size_t)row * KP2_D;
    for (int i = tid; i < DIM; i += 256) {
        float v = (xr[i] - mean) * inv * w[i] + b[i];
        __half hi = __float2half(v);
        yr[i] = hi;
        yr[DIM + i] = __float2half(v - __half2float(hi));
    }
}

__global__ void im2col_split(const float* __restrict__ img, __half* __restrict__ a16)
{
    int idx = blockIdx.x * blockDim.x + threadIdx.x;
    if (idx >= PATCH_ROWS * DIM) return;
    int e = idx % DIM;
    int m = idx / DIM;
    int b = m / NPATCH, p = m % NPATCH;
    int gr = p / 14, gc = p % 14;
    int c = e % 3;
    int pp = e / 3;
    int pr = pp / 16, pc = pp % 16;
    float v = img[(((size_t)b * 3 + c) * 224 + gr * 16 + pr) * 224 + gc * 16 + pc];
    __half hi = __float2half(v);
    __half* dst = a16 + (size_t)m * KP2_D;
    dst[e] = hi;
    dst[DIM + e] = __float2half(v - __half2float(hi));
}

__global__ void assemble_kernel(const float* __restrict__ tokens,
                                const float* __restrict__ cls,
                                const float* __restrict__ pos,
                                float* __restrict__ x)
{
    int idx = blockIdx.x * blockDim.x + threadIdx.x;
    if (idx >= ROWS * DIM) return;
    int d = idx % DIM;
    int r = idx / DIM;
    int b = r / TOK, n = r % TOK;
    float v = (n == 0) ? cls[d] : tokens[((size_t)b * NPATCH + (n - 1)) * DIM + d];
    x[idx] = v + pos[(size_t)n * DIM + d];
}

// ===== attention: warp-per-query, fp16 K/V in smem, shuffle softmax =====
#define ATT_PAD 33
#define ATT2_SMEM ((2*TOK*ATT_PAD + 8*ATT_PAD) * 4 + 8*200*4)

__global__ __launch_bounds__(256) void attn2(
    const float* __restrict__ Q, const float* __restrict__ K,
    const float* __restrict__ V, __half* __restrict__ a16)
{
    extern __shared__ char smraw[];
    __half2* ks2 = (__half2*)smraw;
    __half2* vs2 = ks2 + TOK * ATT_PAD;
    __half2* qs2 = vs2 + TOK * ATT_PAD;
    float*   sc  = (float*)(qs2 + 8 * ATT_PAD);

    int bh = blockIdx.x;
    int b = bh / HEADS, h = bh % HEADS;
    int tid = threadIdx.x, lane = tid & 31, w = tid >> 5;
    const float2* Qb = (const float2*)(Q + (size_t)bh * TOK * DHD);
    const float2* Kb = (const float2*)(K + (size_t)bh * TOK * DHD);
    const float2* Vb = (const float2*)(V + (size_t)bh * TOK * DHD);

    for (int i = tid; i < TOK * 32; i += 256) {
        int n = i >> 5, d2 = i & 31;
        float2 kv = Kb[i];
        float2 vv = Vb[i];
        ks2[n * ATT_PAD + d2] = __floats2half2_rn(kv.x, kv.y);
        vs2[n * ATT_PAD + d2] = __floats2half2_rn(vv.x, vv.y);
    }
    __syncthreads();

    float* scw = sc + w * 200;
    for (int base = 0; base < TOK; base += 8) {
        int nq = base + w;
        bool ok = (nq < TOK);
        if (ok) {
            float2 qv = Qb[(size_t)nq * 32 + lane];
            qs2[w * ATT_PAD + lane] = __floats2half2_rn(qv.x, qv.y);
        }
        __syncwarp();
        float mx = -1e30f;
        if (ok) {
            for (int kk = lane; kk < TOK; kk += 32) {
                float s = 0.f;
#pragma unroll
                for (int d2 = 0; d2 < 32; d2++) {
                    float2 kv = __half22float2(ks2[kk * ATT_PAD + d2]);
                    float2 qv = __half22float2(qs2[w * ATT_PAD + d2]);
                    s += kv.x * qv.x + kv.y * qv.y;
                }
                s *= 0.125f;
                scw[kk] = s;
                mx = fmaxf(mx, s);
            }
        }
#pragma unroll
        for (int o = 16; o > 0; o >>= 1) mx = fmaxf(mx, __shfl_xor_sync(0xffffffffu, mx, o));
        float sum = 0.f;
        if (ok) {
            for (int kk = lane; kk < TOK; kk += 32) {
                float p = expf(scw[kk] - mx);
                scw[kk] = p;
                sum += p;
            }
        }
#pragma unroll
        for (int o = 16; o > 0; o >>= 1) sum += __shfl_xor_sync(0xffffffffu, sum, o);
        float inv = 1.f / sum;
        __syncwarp();
        if (ok) {
            float ax = 0.f, ay = 0.f;
            for (int kk = 0; kk < TOK; kk++) {
                float p = scw[kk];
                float2 vv = __half22float2(vs2[kk * ATT_PAD + lane]);
                ax += p * vv.x; ay += p * vv.y;
            }
            ax *= inv; ay *= inv;
            size_t o0 = ((size_t)(b * TOK + nq)) * KP2_D + h * DHD + lane * 2;
            __half h0 = __float2half(ax), h1 = __float2half(ay);
            a16[o0]           = h0;
            a16[o0 + 1]       = h1;
            a16[o0 + DIM]     = __float2half(ax - __half2float(h0));
            a16[o0 + DIM + 1] = __float2half(ay - __half2float(h1));
        }
        __syncwarp();
    }
}

// fp32 SGEMM for the tiny head (M=32)
__global__ __launch_bounds__(256) void sgemm(
    const float* __restrict__ A, int lda,
    const float* __restrict__ W, const float* __restrict__ bias,
    float* __restrict__ C, int ldc, int M, int N, int K, int act)
{
    __shared__ float As[16][128];
    __shared__ float Bs[16][64];
    int tid = threadIdx.x;
    int tx = tid & 15, ty = tid >> 4;
    int row0 = blockIdx.y * 128;
    int col0 = blockIdx.x * 64;
    float acc[8][4];
#pragma unroll
    for (int i = 0; i < 8; i++)
#pragma unroll
        for (int j = 0; j < 4; j++) acc[i][j] = 0.f;
    for (int k0 = 0; k0 < K; k0 += 16) {
#pragma unroll
        for (int i = 0; i < 2; i++) {
            int idx = tid + i * 256;
            int r = idx >> 2, c = (idx & 3) << 2;
            int gr = row0 + r;
            float4 v = make_float4(0.f, 0.f, 0.f, 0.f);
            if (gr < M) v = *(const float4*)(A + (size_t)gr * lda + k0 + c);
            As[c + 0][r] = v.x; As[c + 1][r] = v.y; As[c + 2][r] = v.z; As[c + 3][r] = v.w;
        }
        {
            int n = tid >> 2, c = (tid & 3) << 2;
            int gn = col0 + n;
            float4 v = make_float4(0.f, 0.f, 0.f, 0.f);
            if (gn < N) v = *(const float4*)(W + (size_t)gn * K + k0 + c);
            Bs[c + 0][n] = v.x; Bs[c + 1][n] = v.y; Bs[c + 2][n] = v.z; Bs[c + 3][n] = v.w;
        }
        __syncthreads();
#pragma unroll
        for (int kk = 0; kk < 16; kk++) {
            float4 a0 = *(const float4*)&As[kk][ty * 8];
            float4 a1 = *(const float4*)&As[kk][ty * 8 + 4];
            float4 bb = *(const float4*)&Bs[kk][tx * 4];
            float av[8] = {a0.x, a0.y, a0.z, a0.w, a1.x, a1.y, a1.z, a1.w};
            float bv[4] = {bb.x, bb.y, bb.z, bb.w};
#pragma unroll
            for (int i = 0; i < 8; i++)
#pragma unroll
                for (int j = 0; j < 4; j++) acc[i][j] += av[i] * bv[j];
        }
        __syncthreads();
    }
#pragma unroll
    for (int i = 0; i < 8; i++) {
        int gr = row0 + ty * 8 + i;
        if (gr >= M) continue;
#pragma unroll
        for (int j = 0; j < 4; j++) {
            int gn = col0 + tx * 4 + j;
            if (gn >= N) continue;
            float v = acc[i][j];
            if (bias) v += bias[gn];
            if (act == 2) v = tanhf(v);
            C[(size_t)gr * ldc + gn] = v;
        }
    }
}

extern "C" void kernel_launch(void* const* d_in, const int* in_sizes, int n_in,
                              void* d_out, int out_size)
{
    const float* img     = (const float*)d_in[0];
    const float* patch_w = (const float*)d_in[1];
    const float* patch_b = (const float*)d_in[2];
    const float* cls_tok = (const float*)d_in[3];
    const float* pos_emb = (const float*)d_in[4];
    const float* ln1_w   = (const float*)d_in[5];
    const float* ln1_b   = (const float*)d_in[6];
    const float* qkv_w   = (const float*)d_in[7];
    const float* qkv_b   = (const float*)d_in[8];
    const float* proj_w  = (const float*)d_in[9];
    const float* proj_b  = (const float*)d_in[10];
    const float* ln2_w   = (const float*)d_in[11];
    const float* ln2_b   = (const float*)d_in[12];
    const float* ff1_w   = (const float*)d_in[13];
    const float* ff1_b   = (const float*)d_in[14];
    const float* ff2_w   = (const float*)d_in[15];
    const float* ff2_b   = (const float*)d_in[16];
    const float* head1_w = (const float*)d_in[17];
    const float* head1_b = (const float*)d_in[18];
    const float* head2_w = (const float*)d_in[19];
    const float* head2_b = (const float*)d_in[20];
    float* out = (float*)d_out;

    float *x, *q, *k, *v, *tok, *hh;
    __half *a16, *f16, *wp, *wq, *wpr, *wf1, *wf2;
    cudaGetSymbolAddress((void**)&x,   g_x);
    cudaGetSymbolAddress((void**)&q,   g_q);
    cudaGetSymbolAddress((void**)&k,   g_kk);
    cudaGetSymbolAddress((void**)&v,   g_v);
    cudaGetSymbolAddress((void**)&tok, g_tok);
    cudaGetSymbolAddress((void**)&hh,  g_hh);
    cudaGetSymbolAddress((void**)&a16, g_a16);
    cudaGetSymbolAddress((void**)&f16, g_f16);
    cudaGetSymbolAddress((void**)&wp,  g_wp16);
    cudaGetSymbolAddress((void**)&wq,  g_wqkv16);
    cudaGetSymbolAddress((void**)&wpr, g_wpr16);
    cudaGetSymbolAddress((void**)&wf1, g_wf1_16);
    cudaGetSymbolAddress((void**)&wf2, g_wf2_16);

    cudaFuncSetAttribute(hgemm, cudaFuncAttributeMaxDynamicSharedMemorySize, HG_SMEM);
    cudaFuncSetAttribute(attn2, cudaFuncAttributeMaxDynamicSharedMemorySize, ATT2_SMEM);

    long t;
    // launch order arranged so 0-indexed launch #4 is an hgemm (ncu capture slot)
    t = (long)DIM * DIM;                                                    // 0
    convert_w<<<(unsigned)((t + 255) / 256), 256>>>(patch_w, wp, t);
    int tot = PATCH_ROWS * DIM;                                             // 1
    im2col_split<<<(tot + 255) / 256, 256>>>(img, a16);
    t = 12L * QKVD * DIM;                                                   // 2
    convert_w<<<(unsigned)((t + 255) / 256), 256>>>(qkv_w, wq, t);
    t = 12L * DIM * DIM;                                                    // 3
    convert_w<<<(unsigned)((t + 255) / 256), 256>>>(proj_w, wpr, t);
    hgemm<<<dim3(6, 49), 256, HG_SMEM>>>(a16, wp, DIM, patch_b,             // 4  <- ncu
                                         (const float*)0, tok, (__half*)0,
                                         (float*)0, (float*)0, (float*)0,
                                         DIM, PATCH_ROWS, 0);
    int tot2 = ROWS * DIM;                                                  // 5
    assemble_kernel<<<(tot2 + 255) / 256, 256>>>(tok, cls_tok, pos_emb, x);
    t = 12L * FFD * DIM;                                                    // 6
    convert_w<<<(unsigned)((t + 255) / 256), 256>>>(ff1_w, wf1, t);
    t = 12L * DIM * FFD;                                                    // 7
    convert_w<<<(unsigned)((t + 255) / 256), 256>>>(ff2_w, wf2, t);

    for (int l = 0; l < 12; l++) {
        ln_split<<<ROWS, 256>>>(x, ln1_w + (size_t)l * DIM, ln1_b + (size_t)l * DIM, a16);
        hgemm<<<dim3(18, 50), 256, HG_SMEM>>>(a16, wq + (size_t)l * QKVD * DIM, DIM,
                                              qkv_b + (size_t)l * QKVD, (const float*)0,
                                              (float*)0, (__half*)0, q, k, v,
                                              QKVD, ROWS, 3);
        attn2<<<BATCH * HEADS, 256, ATT2_SMEM>>>(q, k, v, a16);
        hgemm<<<dim3(6, 50), 256, HG_SMEM>>>(a16, wpr + (size_t)l * DIM * DIM, DIM,
                                             proj_b + (size_t)l * DIM, x,
                                             x, (__half*)0, (float*)0, (float*)0, (float*)0,
                                             DIM, ROWS, 1);
        ln_split<<<ROWS, 256>>>(x, ln2_w + (size_t)l * DIM, ln2_b + (size_t)l * DIM, a16);
        hgemm<<<dim3(24, 50), 256, HG_SMEM>>>(a16, wf1 + (size_t)l * FFD * DIM, DIM,
                                              ff1_b + (size_t)l * FFD, (const float*)0,
                                              (float*)0, f16, (float*)0, (float*)0, (float*)0,
                                              FFD, ROWS, 2);
        hgemm<<<dim3(6, 50), 256, HG_SMEM>>>(f16, wf2 + (size_t)l * DIM * FFD, FFD,
                                             ff2_b + (size_t)l * DIM, x,
                                             x, (__half*)0, (float*)0, (float*)0, (float*)0,
                                             DIM, ROWS, 1);
    }

    sgemm<<<dim3(48, 1), 256>>>(x, TOK * DIM, head1_w, head1_b, hh, FFD, BATCH, FFD, DIM, 2);
    sgemm<<<dim3(16, 1), 256>>>(hh, FFD, head2_w, head2_b, out, NCLSD, BATCH, NCLSD, FFD, 0);
}

// round 8
// speedup vs baseline: 3.9561x; 1.0154x over previous
#include <cuda_runtime.h>
#include <cuda_fp16.h>
#include <math.h>
#include <stdint.h>

#define BATCH 32
#define TOK 197
#define ROWS (BATCH*TOK)
#define MPAD 6400
#define DIM 768
#define HEADS 12
#define DHD 64
#define FFD 3072
#define QKVD 2304
#define NPATCH 196
#define PATCH_ROWS (BATCH*NPATCH)
#define NCLSD 1000
#define KP2_D (2*DIM)
#define KP2_F (2*FFD)

__device__ float  g_x   [ROWS*DIM];
__device__ __align__(128) __half g_q16 [BATCH*HEADS*TOK*DHD];
__device__ __align__(128) __half g_k16 [BATCH*HEADS*TOK*DHD];
__device__ __align__(128) __half g_v16 [BATCH*HEADS*TOK*DHD];
__device__ float  g_tok [PATCH_ROWS*DIM];
__device__ float  g_hh  [BATCH*FFD];
__device__ __align__(128) __half g_a16 [MPAD*KP2_D];
__device__ __align__(128) __half g_f16 [(size_t)MPAD*KP2_F];
__device__ __align__(128) __half g_wp16  [DIM*DIM];
__device__ __align__(128) __half g_wqkv16[(size_t)12*QKVD*DIM];
__device__ __align__(128) __half g_wpr16 [(size_t)12*DIM*DIM];
__device__ __align__(128) __half g_wf1_16[(size_t)12*FFD*DIM];
__device__ __align__(128) __half g_wf2_16[(size_t)12*DIM*FFD];

__device__ __forceinline__ uint32_t smem_u32(const void* p) {
    uint32_t a;
    asm("{ .reg .u64 t; cvta.to.shared.u64 t, %1; cvt.u32.u64 %0, t; }" : "=r"(a) : "l"(p));
    return a;
}
__device__ __forceinline__ void cp_async16(uint32_t s, const void* g) {
    asm volatile("cp.async.cg.shared.global [%0], [%1], 16;\n" :: "r"(s), "l"(g));
}
#define CP_COMMIT() asm volatile("cp.async.commit_group;\n" ::: "memory")
#define CP_WAIT(n)  asm volatile("cp.async.wait_group %0;\n" :: "n"(n) : "memory")

__device__ __forceinline__ void ldsm_x4(uint32_t& r0, uint32_t& r1, uint32_t& r2, uint32_t& r3,
                                        uint32_t addr) {
    asm volatile("ldmatrix.sync.aligned.m8n8.x4.shared.b16 {%0,%1,%2,%3}, [%4];"
                 : "=r"(r0), "=r"(r1), "=r"(r2), "=r"(r3) : "r"(addr));
}
__device__ __forceinline__ void mma16816(float* c, const uint32_t* a, const uint32_t* b) {
    asm volatile("mma.sync.aligned.m16n8k16.row.col.f32.f16.f16.f32 "
        "{%0,%1,%2,%3}, {%4,%5,%6,%7}, {%8,%9}, {%0,%1,%2,%3};"
        : "+f"(c[0]), "+f"(c[1]), "+f"(c[2]), "+f"(c[3])
        : "r"(a[0]), "r"(a[1]), "r"(a[2]), "r"(a[3]), "r"(b[0]), "r"(b[1]));
}
__device__ __forceinline__ float gelu_f(float v) {
    return 0.5f * v * (1.0f + erff(v * 0.70710678118654752f));
}
__device__ __forceinline__ float wred_sum(float v) {
#pragma unroll
    for (int o = 16; o > 0; o >>= 1) v += __shfl_xor_sync(0xffffffffu, v, o);
    return v;
}

// ===== split-fp16 HMMA GEMM: A=[hi|lo], B=fp16, 2 products, 4-stage pipeline =====
#define STAGE3 24576
#define HG_SMEM (4*STAGE3)

__global__ __launch_bounds__(256, 2) void hgemm(
    const __half* __restrict__ A, const __half* __restrict__ B, int K,
    const float* __restrict__ bias, const float* __restrict__ res,
    float* __restrict__ outF, __half* __restrict__ out16,
    __half* __restrict__ gq, __half* __restrict__ gk, __half* __restrict__ gv,
    int ldc, int M, int mode)
{
    extern __shared__ char smraw[];
    uint32_t smb = smem_u32(smraw);
    int tid = threadIdx.x;
    int lane = tid & 31, wid = tid >> 5;
    int warp_m = wid & 1, warp_n = wid >> 1;
    int row0 = blockIdx.y * 128, col0 = blockIdx.x * 128;

    int a_row0 = (tid + 0)   >> 2, a_c0 = (tid + 0)   & 3;
    int a_row1 = (tid + 256) >> 2, a_c1 = (tid + 256) & 3;
    uint32_t a_s0 = a_row0 * 64 + ((a_c0 ^ ((a_row0 >> 1) & 3)) << 4);
    uint32_t a_s1 = a_row1 * 64 + ((a_c1 ^ ((a_row1 >> 1) & 3)) << 4);

    int g = lane >> 3, l = lane & 7;
    uint32_t a_r64[4], a_rx[4];
#pragma unroll
    for (int mi = 0; mi < 4; mi++) {
        int r = warp_m * 64 + mi * 16 + (g & 1) * 8 + l;
        a_r64[mi] = r * 64; a_rx[mi] = (r >> 1) & 3;
    }
    uint32_t b_r64[2], b_rx[2];
#pragma unroll
    for (int j2 = 0; j2 < 2; j2++) {
        int r = warp_n * 32 + j2 * 16 + (g >> 1) * 8 + l;
        b_r64[j2] = r * 64; b_rx[j2] = (r >> 1) & 3;
    }

    float acc[4][4][4];
#pragma unroll
    for (int mi = 0; mi < 4; mi++)
#pragma unroll
        for (int nj = 0; nj < 4; nj++)
#pragma unroll
            for (int q = 0; q < 4; q++) acc[mi][nj][q] = 0.f;

    const int KT = K >> 5;
    const size_t strA = (size_t)(2 * K);
    const size_t strB = (size_t)K;

#define LOAD_ST(s, kb) do { \
    uint32_t sa = smb + (uint32_t)(s) * STAGE3; \
    const __half* gA = A + (size_t)(row0) * strA + (size_t)(kb) * 32; \
    cp_async16(sa + a_s0, gA + (size_t)a_row0 * strA + a_c0 * 8); \
    cp_async16(sa + a_s1, gA + (size_t)a_row1 * strA + a_c1 * 8); \
    cp_async16(sa + 8192u + a_s0, gA + (size_t)a_row0 * strA + K + a_c0 * 8); \
    cp_async16(sa + 8192u + a_s1, gA + (size_t)a_row1 * strA + K + a_c1 * 8); \
    const __half* gB = B + (size_t)(col0) * strB + (size_t)(kb) * 32; \
    cp_async16(sa + 16384u + a_s0, gB + (size_t)a_row0 * strB + a_c0 * 8); \
    cp_async16(sa + 16384u + a_s1, gB + (size_t)a_row1 * strB + a_c1 * 8); \
} while (0)

    LOAD_ST(0, 0); CP_COMMIT();
    LOAD_ST(1, 1); CP_COMMIT();
    LOAD_ST(2, 2); CP_COMMIT();

    int cur = 0;
    for (int i = 0; i < KT; i++) {
        CP_WAIT(2);
        __syncthreads();
        if (i + 3 < KT) {
            int sp = cur + 3; if (sp >= 4) sp -= 4;
            LOAD_ST(sp, i + 3);
        }
        CP_COMMIT();

        uint32_t ah_b = smb + (uint32_t)cur * STAGE3;
        uint32_t al_b = ah_b + 8192u;
        uint32_t bh_b = ah_b + 16384u;
#pragma unroll
        for (int ks = 0; ks < 2; ks++) {
            uint32_t cha = (uint32_t)(ks * 2 + (g >> 1));
            uint32_t chb = (uint32_t)(ks * 2 + (g & 1));
            uint32_t afh[4][4], afl[4][4], bf[4][2];
            // issue ALL smem loads first, then the uninterrupted MMA stream
#pragma unroll
            for (int mi = 0; mi < 4; mi++)
                ldsm_x4(afh[mi][0], afh[mi][1], afh[mi][2], afh[mi][3],
                        ah_b + a_r64[mi] + ((cha ^ a_rx[mi]) << 4));
#pragma unroll
            for (int j2 = 0; j2 < 2; j2++)
                ldsm_x4(bf[j2 * 2][0], bf[j2 * 2][1], bf[j2 * 2 + 1][0], bf[j2 * 2 + 1][1],
                        bh_b + b_r64[j2] + ((chb ^ b_rx[j2]) << 4));
#pragma unroll
            for (int mi = 0; mi < 4; mi++)
                ldsm_x4(afl[mi][0], afl[mi][1], afl[mi][2], afl[mi][3],
                        al_b + a_r64[mi] + ((cha ^ a_rx[mi]) << 4));
#pragma unroll
            for (int mi = 0; mi < 4; mi++)
#pragma unroll
                for (int nj = 0; nj < 4; nj++)
                    mma16816(acc[mi][nj], afh[mi], bf[nj]);
#pragma unroll
            for (int mi = 0; mi < 4; mi++)
#pragma unroll
                for (int nj = 0; nj < 4; nj++)
                    mma16816(acc[mi][nj], afl[mi], bf[nj]);
        }
        cur++; if (cur >= 4) cur = 0;
    }

    int qrow = lane >> 2, qcol = (lane & 3) * 2;
#pragma unroll
    for (int mi = 0; mi < 4; mi++) {
        int rbase = row0 + warp_m * 64 + mi * 16 + qrow;
#pragma unroll
        for (int half = 0; half < 2; half++) {
            int r = rbase + half * 8;
            if (r >= M) continue;
            int rb = r / TOK, rn = r - rb * TOK;
#pragma unroll
            for (int nj = 0; nj < 4; nj++) {
                int c = col0 + warp_n * 32 + nj * 8 + qcol;
                float v0 = acc[mi][nj][half * 2 + 0] + __ldg(bias + c);
                float v1 = acc[mi][nj][half * 2 + 1] + __ldg(bias + c + 1);
                if (mode == 2) {
                    float g0 = gelu_f(v0), g1 = gelu_f(v1);
                    __half h0 = __float2half(g0), h1 = __float2half(g1);
                    __half l0 = __float2half(g0 - __half2float(h0));
                    __half l1 = __float2half(g1 - __half2float(h1));
                    __half* o = out16 + (size_t)r * (2 * ldc) + c;
                    *(__half2*)(o)       = __halves2half2(h0, h1);
                    *(__half2*)(o + ldc) = __halves2half2(l0, l1);
                } else if (mode == 3) {
#pragma unroll
                    for (int e = 0; e < 2; e++) {
                        int cc = c + e;
                        float vv = e ? v1 : v0;
                        int hh = cc / 192;
                        int t  = cc - hh * 192;
                        int dd = t / 3;
                        int ss = t - dd * 3;
                        __half* dst = (ss == 0) ? gq : (ss == 1) ? gk : gv;
                        dst[(((size_t)(rb * HEADS + hh)) * TOK + rn) * DHD + dd] = __float2half(vv);
                    }
                } else {
                    float* o = outF + (size_t)r * ldc + c;
                    if (mode == 1) {
                        const float* rr = res + (size_t)r * ldc + c;
                        v0 += rr[0]; v1 += rr[1];
                    }
                    *(float2*)o = make_float2(v0, v1);
                }
            }
        }
    }
}

// ===== helpers =====
__global__ void convert_w(const float4* __restrict__ W, __half2* __restrict__ W16, long total4)
{
    long idx = (long)blockIdx.x * blockDim.x + threadIdx.x;
    if (idx >= total4) return;
    float4 v = W[idx];
    W16[idx * 2]     = __halves2half2(__float2half(v.x), __float2half(v.y));
    W16[idx * 2 + 1] = __halves2half2(__float2half(v.z), __float2half(v.w));
}

// warp-per-row LayerNorm -> [hi|lo]
__global__ __launch_bounds__(256) void ln_split_warp(
    const float* __restrict__ x, const float* __restrict__ w,
    const float* __restrict__ b, __half* __restrict__ y16)
{
    int row = blockIdx.x * 8 + (threadIdx.x >> 5);
    if (row >= ROWS) return;
    int lane = threadIdx.x & 31;
    const float4* xr = (const float4*)(x + (size_t)row * DIM);
    float4 vx[6];
    float s = 0.f;
#pragma unroll
    for (int i = 0; i < 6; i++) {
        vx[i] = xr[lane + 32 * i];
        s += (vx[i].x + vx[i].y) + (vx[i].z + vx[i].w);
    }
    s = wred_sum(s);
    float mean = s * (1.0f / 768.f);
    float s2 = 0.f;
#pragma unroll
    for (int i = 0; i < 6; i++) {
        float a0 = vx[i].x - mean, a1 = vx[i].y - mean;
        float a2 = vx[i].z - mean, a3 = vx[i].w - mean;
        s2 += a0 * a0 + a1 * a1 + a2 * a2 + a3 * a3;
    }
    s2 = wred_sum(s2);
    float inv = rsqrtf(s2 * (1.0f / 768.f) + 1e-5f);
    const float4* wr = (const float4*)w;
    const float4* br = (const float4*)b;
    __half2* yh = (__half2*)(y16 + (size_t)row * KP2_D);
    __half2* yl = (__half2*)(y16 + (size_t)row * KP2_D + DIM);
#pragma unroll
    for (int i = 0; i < 6; i++) {
        int c4 = lane + 32 * i;
        float4 w4 = wr[c4], b4 = br[c4];
        float v0 = (vx[i].x - mean) * inv * w4.x + b4.x;
        float v1 = (vx[i].y - mean) * inv * w4.y + b4.y;
        float v2 = (vx[i].z - mean) * inv * w4.z + b4.z;
        float v3 = (vx[i].w - mean) * inv * w4.w + b4.w;
        __half h0 = __float2half(v0), h1 = __float2half(v1);
        __half h2 = __float2half(v2), h3 = __float2half(v3);
        yh[c4 * 2]     = __halves2half2(h0, h1);
        yh[c4 * 2 + 1] = __halves2half2(h2, h3);
        yl[c4 * 2]     = __halves2half2(__float2half(v0 - __half2float(h0)),
                                        __float2half(v1 - __half2float(h1)));
        yl[c4 * 2 + 1] = __halves2half2(__float2half(v2 - __half2float(h2)),
                                        __float2half(v3 - __half2float(h3)));
    }
}

__global__ void im2col_split(const float* __restrict__ img, __half* __restrict__ a16)
{
    int idx = blockIdx.x * blockDim.x + threadIdx.x;
    if (idx >= PATCH_ROWS * DIM) return;
    int e = idx % DIM;
    int m = idx / DIM;
    int b = m / NPATCH, p = m % NPATCH;
    int gr = p / 14, gc = p % 14;
    int c = e % 3;
    int pp = e / 3;
    int pr = pp / 16, pc = pp % 16;
    float v = img[(((size_t)b * 3 + c) * 224 + gr * 16 + pr) * 224 + gc * 16 + pc];
    __half hi = __float2half(v);
    __half* dst = a16 + (size_t)m * KP2_D;
    dst[e] = hi;
    dst[DIM + e] = __float2half(v - __half2float(hi));
}

__global__ void assemble_kernel(const float* __restrict__ tokens,
                                const float* __restrict__ cls,
                                const float* __restrict__ pos,
                                float* __restrict__ x)
{
    int idx = blockIdx.x * blockDim.x + threadIdx.x;
    if (idx >= ROWS * DIM) return;
    int d = idx % DIM;
    int r = idx / DIM;
    int b = r / TOK, n = r % TOK;
    float v = (n == 0) ? cls[d] : tokens[((size_t)b * NPATCH + (n - 1)) * DIM + d];
    x[idx] = v + pos[(size_t)n * DIM + d];
}

// ===== attention: warp-per-query, fp16 K/V (direct half2 smem copy) =====
#define ATT_PAD 33
#define ATT2_SMEM ((2*TOK*ATT_PAD + 8*ATT_PAD) * 4 + 8*200*4)

__global__ __launch_bounds__(256) void attn2(
    const __half* __restrict__ Q, const __half* __restrict__ K,
    const __half* __restrict__ V, __half* __restrict__ a16)
{
    extern __shared__ char smraw[];
    __half2* ks2 = (__half2*)smraw;
    __half2* vs2 = ks2 + TOK * ATT_PAD;
    __half2* qs2 = vs2 + TOK * ATT_PAD;
    float*   sc  = (float*)(qs2 + 8 * ATT_PAD);

    int bh = blockIdx.x;
    int b = bh / HEADS, h = bh % HEADS;
    int tid = threadIdx.x, lane = tid & 31, w = tid >> 5;
    const __half2* Qb = (const __half2*)(Q + (size_t)bh * TOK * DHD);
    const __half2* Kb = (const __half2*)(K + (size_t)bh * TOK * DHD);
    const __half2* Vb = (const __half2*)(V + (size_t)bh * TOK * DHD);

    for (int i = tid; i < TOK * 32; i += 256) {
        int n = i >> 5, d2 = i & 31;
        ks2[n * ATT_PAD + d2] = Kb[i];
        vs2[n * ATT_PAD + d2] = Vb[i];
    }
    __syncthreads();

    float* scw = sc + w * 200;
    for (int base = 0; base < TOK; base += 8) {
        int nq = base + w;
        bool ok = (nq < TOK);
        if (ok) qs2[w * ATT_PAD + lane] = Qb[(size_t)nq * 32 + lane];
        __syncwarp();
        float mx = -1e30f;
        if (ok) {
            for (int kk = lane; kk < TOK; kk += 32) {
                float s = 0.f;
#pragma unroll
                for (int d2 = 0; d2 < 32; d2++) {
                    float2 kv = __half22float2(ks2[kk * ATT_PAD + d2]);
                    float2 qv = __half22float2(qs2[w * ATT_PAD + d2]);
                    s += kv.x * qv.x + kv.y * qv.y;
                }
                s *= 0.125f;
                scw[kk] = s;
                mx = fmaxf(mx, s);
            }
        }
#pragma unroll
        for (int o = 16; o > 0; o >>= 1) mx = fmaxf(mx, __shfl_xor_sync(0xffffffffu, mx, o));
        float sum = 0.f;
        if (ok) {
            for (int kk = lane; kk < TOK; kk += 32) {
                float p = expf(scw[kk] - mx);
                scw[kk] = p;
                sum += p;
            }
        }
#pragma unroll
        for (int o = 16; o > 0; o >>= 1) sum += __shfl_xor_sync(0xffffffffu, sum, o);
        float inv = 1.f / sum;
        __syncwarp();
        if (ok) {
            float ax = 0.f, ay = 0.f;
            for (int kk = 0; kk < TOK; kk++) {
                float p = scw[kk];
                float2 vv = __half22float2(vs2[kk * ATT_PAD + lane]);
                ax += p * vv.x; ay += p * vv.y;
            }
            ax *= inv; ay *= inv;
            size_t o0 = ((size_t)(b * TOK + nq)) * KP2_D + h * DHD + lane * 2;
            __half h0 = __float2half(ax), h1 = __float2half(ay);
            a16[o0]           = h0;
            a16[o0 + 1]       = h1;
            a16[o0 + DIM]     = __float2half(ax - __half2float(h0));
            a16[o0 + DIM + 1] = __float2half(ay - __half2float(h1));
        }
        __syncwarp();
    }
}

// fp32 SGEMM for the tiny head (M=32)
__global__ __launch_bounds__(256) void sgemm(
    const float* __restrict__ A, int lda,
    const float* __restrict__ W, const float* __restrict__ bias,
    float* __restrict__ C, int ldc, int M, int N, int K, int act)
{
    __shared__ float As[16][128];
    __shared__ float Bs[16][64];
    int tid = threadIdx.x;
    int tx = tid & 15, ty = tid >> 4;
    int row0 = blockIdx.y * 128;
    int col0 = blockIdx.x * 64;
    float acc[8][4];
#pragma unroll
    for (int i = 0; i < 8; i++)
#pragma unroll
        for (int j = 0; j < 4; j++) acc[i][j] = 0.f;
    for (int k0 = 0; k0 < K; k0 += 16) {
#pragma unroll
        for (int i = 0; i < 2; i++) {
            int idx = tid + i * 256;
            int r = idx >> 2, c = (idx & 3) << 2;
            int gr = row0 + r;
            float4 v = make_float4(0.f, 0.f, 0.f, 0.f);
            if (gr < M) v = *(const float4*)(A + (size_t)gr * lda + k0 + c);
            As[c + 0][r] = v.x; As[c + 1][r] = v.y; As[c + 2][r] = v.z; As[c + 3][r] = v.w;
        }
        {
            int n = tid >> 2, c = (tid & 3) << 2;
            int gn = col0 + n;
            float4 v = make_float4(0.f, 0.f, 0.f, 0.f);
            if (gn < N) v = *(const float4*)(W + (size_t)gn * K + k0 + c);
            Bs[c + 0][n] = v.x; Bs[c + 1][n] = v.y; Bs[c + 2][n] = v.z; Bs[c + 3][n] = v.w;
        }
        __syncthreads();
#pragma unroll
        for (int kk = 0; kk < 16; kk++) {
            float4 a0 = *(const float4*)&As[kk][ty * 8];
            float4 a1 = *(const float4*)&As[kk][ty * 8 + 4];
            float4 bb = *(const float4*)&Bs[kk][tx * 4];
            float av[8] = {a0.x, a0.y, a0.z, a0.w, a1.x, a1.y, a1.z, a1.w};
            float bv[4] = {bb.x, bb.y, bb.z, bb.w};
#pragma unroll
            for (int i = 0; i < 8; i++)
#pragma unroll
                for (int j = 0; j < 4; j++) acc[i][j] += av[i] * bv[j];
        }
        __syncthreads();
    }
#pragma unroll
    for (int i = 0; i < 8; i++) {
        int gr = row0 + ty * 8 + i;
        if (gr >= M) continue;
#pragma unroll
        for (int j = 0; j < 4; j++) {
            int gn = col0 + tx * 4 + j;
            if (gn >= N) continue;
            float v = acc[i][j];
            if (bias) v += bias[gn];
            if (act == 2) v = tanhf(v);
            C[(size_t)gr * ldc + gn] = v;
        }
    }
}

extern "C" void kernel_launch(void* const* d_in, const int* in_sizes, int n_in,
                              void* d_out, int out_size)
{
    const float* img     = (const float*)d_in[0];
    const float* patch_w = (const float*)d_in[1];
    const float* patch_b = (const float*)d_in[2];
    const float* cls_tok = (const float*)d_in[3];
    const float* pos_emb = (const float*)d_in[4];
    const float* ln1_w   = (const float*)d_in[5];
    const float* ln1_b   = (const float*)d_in[6];
    const float* qkv_w   = (const float*)d_in[7];
    const float* qkv_b   = (const float*)d_in[8];
    const float* proj_w  = (const float*)d_in[9];
    const float* proj_b  = (const float*)d_in[10];
    const float* ln2_w   = (const float*)d_in[11];
    const float* ln2_b   = (const float*)d_in[12];
    const float* ff1_w   = (const float*)d_in[13];
    const float* ff1_b   = (const float*)d_in[14];
    const float* ff2_w   = (const float*)d_in[15];
    const float* ff2_b   = (const float*)d_in[16];
    const float* head1_w = (const float*)d_in[17];
    const float* head1_b = (const float*)d_in[18];
    const float* head2_w = (const float*)d_in[19];
    const float* head2_b = (const float*)d_in[20];
    float* out = (float*)d_out;

    float *x, *tok, *hh;
    __half *q, *k, *v, *a16, *f16, *wp, *wq, *wpr, *wf1, *wf2;
    cudaGetSymbolAddress((void**)&x,   g_x);
    cudaGetSymbolAddress((void**)&q,   g_q16);
    cudaGetSymbolAddress((void**)&k,   g_k16);
    cudaGetSymbolAddress((void**)&v,   g_v16);
    cudaGetSymbolAddress((void**)&tok, g_tok);
    cudaGetSymbolAddress((void**)&hh,  g_hh);
    cudaGetSymbolAddress((void**)&a16, g_a16);
    cudaGetSymbolAddress((void**)&f16, g_f16);
    cudaGetSymbolAddress((void**)&wp,  g_wp16);
    cudaGetSymbolAddress((void**)&wq,  g_wqkv16);
    cudaGetSymbolAddress((void**)&wpr, g_wpr16);
    cudaGetSymbolAddress((void**)&wf1, g_wf1_16);
    cudaGetSymbolAddress((void**)&wf2, g_wf2_16);

    cudaFuncSetAttribute(hgemm, cudaFuncAttributeMaxDynamicSharedMemorySize, HG_SMEM);
    cudaFuncSetAttribute(attn2, cudaFuncAttributeMaxDynamicSharedMemorySize, ATT2_SMEM);

    long t4;
    t4 = (long)DIM * DIM / 4;
    convert_w<<<(unsigned)((t4 + 255) / 256), 256>>>((const float4*)patch_w, (__half2*)wp, t4);
    t4 = 12L * QKVD * DIM / 4;
    convert_w<<<(unsigned)((t4 + 255) / 256), 256>>>((const float4*)qkv_w, (__half2*)wq, t4);
    t4 = 12L * DIM * DIM / 4;
    convert_w<<<(unsigned)((t4 + 255) / 256), 256>>>((const float4*)proj_w, (__half2*)wpr, t4);
    t4 = 12L * FFD * DIM / 4;
    convert_w<<<(unsigned)((t4 + 255) / 256), 256>>>((const float4*)ff1_w, (__half2*)wf1, t4);
    t4 = 12L * DIM * FFD / 4;
    convert_w<<<(unsigned)((t4 + 255) / 256), 256>>>((const float4*)ff2_w, (__half2*)wf2, t4);

    // patch embed
    {
        int tot = PATCH_ROWS * DIM;
        im2col_split<<<(tot + 255) / 256, 256>>>(img, a16);
        hgemm<<<dim3(6, 49), 256, HG_SMEM>>>(a16, wp, DIM, patch_b, (const float*)0,
                                             tok, (__half*)0, (__half*)0, (__half*)0, (__half*)0,
                                             DIM, PATCH_ROWS, 0);
        int tot2 = ROWS * DIM;
        assemble_kernel<<<(tot2 + 255) / 256, 256>>>(tok, cls_tok, pos_emb, x);
    }

    for (int l = 0; l < 12; l++) {
        ln_split_warp<<<(ROWS + 7) / 8, 256>>>(x, ln1_w + (size_t)l * DIM, ln1_b + (size_t)l * DIM, a16);
        hgemm<<<dim3(18, 50), 256, HG_SMEM>>>(a16, wq + (size_t)l * QKVD * DIM, DIM,
                                              qkv_b + (size_t)l * QKVD, (const float*)0,
                                              (float*)0, (__half*)0, q, k, v,
                                              QKVD, ROWS, 3);
        attn2<<<BATCH * HEADS, 256, ATT2_SMEM>>>(q, k, v, a16);
        hgemm<<<dim3(6, 50), 256, HG_SMEM>>>(a16, wpr + (size_t)l * DIM * DIM, DIM,
                                             proj_b + (size_t)l * DIM, x,
                                             x, (__half*)0, (__half*)0, (__half*)0, (__half*)0,
                                             DIM, ROWS, 1);
        ln_split_warp<<<(ROWS + 7) / 8, 256>>>(x, ln2_w + (size_t)l * DIM, ln2_b + (size_t)l * DIM, a16);
        hgemm<<<dim3(24, 50), 256, HG_SMEM>>>(a16, wf1 + (size_t)l * FFD * DIM, DIM,
                                              ff1_b + (size_t)l * FFD, (const float*)0,
                                              (float*)0, f16, (__half*)0, (__half*)0, (__half*)0,
                                              FFD, ROWS, 2);
        hgemm<<<dim3(6, 50), 256, HG_SMEM>>>(f16, wf2 + (size_t)l * DIM * FFD, FFD,
                                             ff2_b + (size_t)l * DIM, x,
                                             x, (__half*)0, (__half*)0, (__half*)0, (__half*)0,
                                             DIM, ROWS, 1);
    }

    sgemm<<<dim3(48, 1), 256>>>(x, TOK * DIM, head1_w, head1_b, hh, FFD, BATCH, FFD, DIM, 2);
    sgemm<<<dim3(16, 1), 256>>>(hh, FFD, head2_w, head2_b, out, NCLSD, BATCH, NCLSD, FFD, 0);
}

// round 9
// speedup vs baseline: 4.4828x; 1.1331x over previous
#include <cuda_runtime.h>
#include <cuda_fp16.h>
#include <math.h>
#include <stdint.h>

#define BATCH 32
#define TOK 197
#define ROWS (BATCH*TOK)
#define MPAD 6400
#define DIM 768
#define HEADS 12
#define DHD 64
#define FFD 3072
#define QKVD 2304
#define NPATCH 196
#define PATCH_ROWS (BATCH*NPATCH)
#define NCLSD 1000
#define KP2_D (2*DIM)
#define KP2_F (2*FFD)

__device__ float  g_x   [ROWS*DIM];
__device__ __align__(128) __half g_q16 [BATCH*HEADS*TOK*DHD];
__device__ __align__(128) __half g_k16 [BATCH*HEADS*TOK*DHD];
__device__ __align__(128) __half g_v16 [BATCH*HEADS*TOK*DHD];
__device__ float  g_tok [PATCH_ROWS*DIM];
__device__ float  g_hh  [BATCH*FFD];
__device__ __align__(128) __half g_a16 [MPAD*KP2_D];
__device__ __align__(128) __half g_f16 [(size_t)MPAD*KP2_F];
__device__ __align__(128) __half g_wp16  [DIM*DIM];
__device__ __align__(128) __half g_wqkv16[(size_t)12*QKVD*DIM];
__device__ __align__(128) __half g_wpr16 [(size_t)12*DIM*DIM];
__device__ __align__(128) __half g_wf1_16[(size_t)12*FFD*DIM];
__device__ __align__(128) __half g_wf2_16[(size_t)12*DIM*FFD];

__device__ __forceinline__ uint32_t smem_u32(const void* p) {
    uint32_t a;
    asm("{ .reg .u64 t; cvta.to.shared.u64 t, %1; cvt.u32.u64 %0, t; }" : "=r"(a) : "l"(p));
    return a;
}
__device__ __forceinline__ void cp_async16(uint32_t s, const void* g) {
    asm volatile("cp.async.cg.shared.global [%0], [%1], 16;\n" :: "r"(s), "l"(g));
}
#define CP_COMMIT() asm volatile("cp.async.commit_group;\n" ::: "memory")
#define CP_WAIT(n)  asm volatile("cp.async.wait_group %0;\n" :: "n"(n) : "memory")

__device__ __forceinline__ void ldsm_x4(uint32_t& r0, uint32_t& r1, uint32_t& r2, uint32_t& r3,
                                        uint32_t addr) {
    asm volatile("ldmatrix.sync.aligned.m8n8.x4.shared.b16 {%0,%1,%2,%3}, [%4];"
                 : "=r"(r0), "=r"(r1), "=r"(r2), "=r"(r3) : "r"(addr));
}
__device__ __forceinline__ void mma16816(float* c, const uint32_t* a, const uint32_t* b) {
    asm volatile("mma.sync.aligned.m16n8k16.row.col.f32.f16.f16.f32 "
        "{%0,%1,%2,%3}, {%4,%5,%6,%7}, {%8,%9}, {%0,%1,%2,%3};"
        : "+f"(c[0]), "+f"(c[1]), "+f"(c[2]), "+f"(c[3])
        : "r"(a[0]), "r"(a[1]), "r"(a[2]), "r"(a[3]), "r"(b[0]), "r"(b[1]));
}
__device__ __forceinline__ float gelu_f(float v) {
    return 0.5f * v * (1.0f + erff(v * 0.70710678118654752f));
}
__device__ __forceinline__ float wred_sum(float v) {
#pragma unroll
    for (int o = 16; o > 0; o >>= 1) v += __shfl_xor_sync(0xffffffffu, v, o);
    return v;
}

// ===== split-fp16 HMMA GEMM: Kc=64 per iter, 2-stage, stage={Ah,Al,B} 48KB =====
#define STG 49152
#define HG_SMEM (2*STG)

__global__ __launch_bounds__(256, 2) void hgemm(
    const __half* __restrict__ A, const __half* __restrict__ B, int K,
    const float* __restrict__ bias, const float* __restrict__ res,
    float* __restrict__ outF, __half* __restrict__ out16,
    __half* __restrict__ gq, __half* __restrict__ gk, __half* __restrict__ gv,
    int ldc, int M, int mode)
{
    extern __shared__ char smraw[];
    uint32_t smb = smem_u32(smraw);
    int tid = threadIdx.x;
    int lane = tid & 31, wid = tid >> 5;
    int warp_m = wid & 1, warp_n = wid >> 1;
    int row0 = blockIdx.y * 128, col0 = blockIdx.x * 128;

    // cp.async mapping: 1024 chunks (128 rows x 8 chunks of 16B) per part, 4/thread
    uint32_t ld_slot[4]; int ld_r[4], ld_c[4];
#pragma unroll
    for (int j = 0; j < 4; j++) {
        int idx = tid + j * 256;
        ld_r[j] = idx >> 3; ld_c[j] = idx & 7;
        ld_slot[j] = (uint32_t)(ld_r[j] * 128 + ((ld_c[j] ^ (ld_r[j] & 7)) << 4));
    }

    int g = lane >> 3, l = lane & 7;
    uint32_t a_roff[4], a_xor[4];
#pragma unroll
    for (int mi = 0; mi < 4; mi++) {
        int r = warp_m * 64 + mi * 16 + (g & 1) * 8 + l;
        a_roff[mi] = r * 128; a_xor[mi] = r & 7;
    }
    uint32_t b_roff[2], b_xor[2];
#pragma unroll
    for (int j2 = 0; j2 < 2; j2++) {
        int r = warp_n * 32 + j2 * 16 + (g >> 1) * 8 + l;
        b_roff[j2] = r * 128; b_xor[j2] = r & 7;
    }

    float acc[4][4][4];
#pragma unroll
    for (int mi = 0; mi < 4; mi++)
#pragma unroll
        for (int nj = 0; nj < 4; nj++)
#pragma unroll
            for (int q = 0; q < 4; q++) acc[mi][nj][q] = 0.f;

    const int KT = K >> 6;
    const size_t strA = (size_t)(2 * K);
    const size_t strB = (size_t)K;
    const __half* gA = A + (size_t)row0 * strA;
    const __half* gB = B + (size_t)col0 * strB;

#define LOAD_ST(s, kb) do { \
    uint32_t sa = smb + (uint32_t)(s) * STG; \
    _Pragma("unroll") \
    for (int j = 0; j < 4; j++) { \
        const __half* pa = gA + (size_t)ld_r[j] * strA + (size_t)(kb) * 64 + ld_c[j] * 8; \
        cp_async16(sa + ld_slot[j], pa); \
        cp_async16(sa + 16384u + ld_slot[j], pa + K); \
        cp_async16(sa + 32768u + ld_slot[j], gB + (size_t)ld_r[j] * strB + (size_t)(kb) * 64 + ld_c[j] * 8); \
    } \
} while (0)

    LOAD_ST(0, 0); CP_COMMIT();

    for (int i = 0; i < KT; i++) {
        CP_WAIT(0);
        __syncthreads();
        if (i + 1 < KT) { LOAD_ST((i + 1) & 1, i + 1); CP_COMMIT(); }

        uint32_t ah_b = smb + (uint32_t)(i & 1) * STG;
        uint32_t al_b = ah_b + 16384u;
        uint32_t bh_b = ah_b + 32768u;
#pragma unroll
        for (int ks = 0; ks < 4; ks++) {
            uint32_t cha = (uint32_t)(ks * 2 + (g >> 1));
            uint32_t chb = (uint32_t)(ks * 2 + (g & 1));
            uint32_t afh[4][4], afl[4][4], bf[4][2];
#pragma unroll
            for (int mi = 0; mi < 4; mi++)
                ldsm_x4(afh[mi][0], afh[mi][1], afh[mi][2], afh[mi][3],
                        ah_b + a_roff[mi] + ((cha ^ a_xor[mi]) << 4));
#pragma unroll
            for (int j2 = 0; j2 < 2; j2++)
                ldsm_x4(bf[j2 * 2][0], bf[j2 * 2][1], bf[j2 * 2 + 1][0], bf[j2 * 2 + 1][1],
                        bh_b + b_roff[j2] + ((chb ^ b_xor[j2]) << 4));
#pragma unroll
            for (int mi = 0; mi < 4; mi++)
                ldsm_x4(afl[mi][0], afl[mi][1], afl[mi][2], afl[mi][3],
                        al_b + a_roff[mi] + ((cha ^ a_xor[mi]) << 4));
#pragma unroll
            for (int mi = 0; mi < 4; mi++)
#pragma unroll
                for (int nj = 0; nj < 4; nj++)
                    mma16816(acc[mi][nj], afh[mi], bf[nj]);
#pragma unroll
            for (int mi = 0; mi < 4; mi++)
#pragma unroll
                for (int nj = 0; nj < 4; nj++)
                    mma16816(acc[mi][nj], afl[mi], bf[nj]);
        }
    }

    int qrow = lane >> 2, qcol = (lane & 3) * 2;
#pragma unroll
    for (int mi = 0; mi < 4; mi++) {
        int rbase = row0 + warp_m * 64 + mi * 16 + qrow;
#pragma unroll
        for (int half = 0; half < 2; half++) {
            int r = rbase + half * 8;
            if (r >= M) continue;
            int rb = r / TOK, rn = r - rb * TOK;
#pragma unroll
            for (int nj = 0; nj < 4; nj++) {
                int c = col0 + warp_n * 32 + nj * 8 + qcol;
                float v0 = acc[mi][nj][half * 2 + 0] + __ldg(bias + c);
                float v1 = acc[mi][nj][half * 2 + 1] + __ldg(bias + c + 1);
                if (mode == 2) {
                    float g0 = gelu_f(v0), g1 = gelu_f(v1);
                    __half h0 = __float2half(g0), h1 = __float2half(g1);
                    __half l0 = __float2half(g0 - __half2float(h0));
                    __half l1 = __float2half(g1 - __half2float(h1));
                    __half* o = out16 + (size_t)r * (2 * ldc) + c;
                    *(__half2*)(o)       = __halves2half2(h0, h1);
                    *(__half2*)(o + ldc) = __halves2half2(l0, l1);
                } else if (mode == 3) {
#pragma unroll
                    for (int e = 0; e < 2; e++) {
                        int cc = c + e;
                        float vv = e ? v1 : v0;
                        int hh = cc / 192;
                        int t  = cc - hh * 192;
                        int dd = t / 3;
                        int ss = t - dd * 3;
                        __half* dst = (ss == 0) ? gq : (ss == 1) ? gk : gv;
                        dst[(((size_t)(rb * HEADS + hh)) * TOK + rn) * DHD + dd] = __float2half(vv);
                    }
                } else {
                    float* o = outF + (size_t)r * ldc + c;
                    if (mode == 1) {
                        const float* rr = res + (size_t)r * ldc + c;
                        v0 += rr[0]; v1 += rr[1];
                    }
                    *(float2*)o = make_float2(v0, v1);
                }
            }
        }
    }
}

// ===== helpers =====
__global__ void convert_w(const float4* __restrict__ W, __half2* __restrict__ W16, long total4)
{
    long idx = (long)blockIdx.x * blockDim.x + threadIdx.x;
    if (idx >= total4) return;
    float4 v = W[idx];
    W16[idx * 2]     = __halves2half2(__float2half(v.x), __float2half(v.y));
    W16[idx * 2 + 1] = __halves2half2(__float2half(v.z), __float2half(v.w));
}

__global__ __launch_bounds__(256) void ln_split_warp(
    const float* __restrict__ x, const float* __restrict__ w,
    const float* __restrict__ b, __half* __restrict__ y16)
{
    int row = blockIdx.x * 8 + (threadIdx.x >> 5);
    if (row >= ROWS) return;
    int lane = threadIdx.x & 31;
    const float4* xr = (const float4*)(x + (size_t)row * DIM);
    float4 vx[6];
    float s = 0.f;
#pragma unroll
    for (int i = 0; i < 6; i++) {
        vx[i] = xr[lane + 32 * i];
        s += (vx[i].x + vx[i].y) + (vx[i].z + vx[i].w);
    }
    s = wred_sum(s);
    float mean = s * (1.0f / 768.f);
    float s2 = 0.f;
#pragma unroll
    for (int i = 0; i < 6; i++) {
        float a0 = vx[i].x - mean, a1 = vx[i].y - mean;
        float a2 = vx[i].z - mean, a3 = vx[i].w - mean;
        s2 += a0 * a0 + a1 * a1 + a2 * a2 + a3 * a3;
    }
    s2 = wred_sum(s2);
    float inv = rsqrtf(s2 * (1.0f / 768.f) + 1e-5f);
    const float4* wr = (const float4*)w;
    const float4* br = (const float4*)b;
    __half2* yh = (__half2*)(y16 + (size_t)row * KP2_D);
    __half2* yl = (__half2*)(y16 + (size_t)row * KP2_D + DIM);
#pragma unroll
    for (int i = 0; i < 6; i++) {
        int c4 = lane + 32 * i;
        float4 w4 = wr[c4], b4 = br[c4];
        float v0 = (vx[i].x - mean) * inv * w4.x + b4.x;
        float v1 = (vx[i].y - mean) * inv * w4.y + b4.y;
        float v2 = (vx[i].z - mean) * inv * w4.z + b4.z;
        float v3 = (vx[i].w - mean) * inv * w4.w + b4.w;
        __half h0 = __float2half(v0), h1 = __float2half(v1);
        __half h2 = __float2half(v2), h3 = __float2half(v3);
        yh[c4 * 2]     = __halves2half2(h0, h1);
        yh[c4 * 2 + 1] = __halves2half2(h2, h3);
        yl[c4 * 2]     = __halves2half2(__float2half(v0 - __half2float(h0)),
                                        __float2half(v1 - __half2float(h1)));
        yl[c4 * 2 + 1] = __halves2half2(__float2half(v2 - __half2float(h2)),
                                        __float2half(v3 - __half2float(h3)));
    }
}

__global__ void im2col_split(const float* __restrict__ img, __half* __restrict__ a16)
{
    int idx = blockIdx.x * blockDim.x + threadIdx.x;
    if (idx >= PATCH_ROWS * DIM) return;
    int e = idx % DIM;
    int m = idx / DIM;
    int b = m / NPATCH, p = m % NPATCH;
    int gr = p / 14, gc = p % 14;
    int c = e % 3;
    int pp = e / 3;
    int pr = pp / 16, pc = pp % 16;
    float v = img[(((size_t)b * 3 + c) * 224 + gr * 16 + pr) * 224 + gc * 16 + pc];
    __half hi = __float2half(v);
    __half* dst = a16 + (size_t)m * KP2_D;
    dst[e] = hi;
    dst[DIM + e] = __float2half(v - __half2float(hi));
}

__global__ void assemble_kernel(const float* __restrict__ tokens,
                                const float* __restrict__ cls,
                                const float* __restrict__ pos,
                                float* __restrict__ x)
{
    int idx = blockIdx.x * blockDim.x + threadIdx.x;
    if (idx >= ROWS * DIM) return;
    int d = idx % DIM;
    int r = idx / DIM;
    int b = r / TOK, n = r % TOK;
    float v = (n == 0) ? cls[d] : tokens[((size_t)b * NPATCH + (n - 1)) * DIM + d];
    x[idx] = v + pos[(size_t)n * DIM + d];
}

// ===== attention: 2 queries per warp, fp16 K/V in smem =====
#define ATT_PAD 33
#define ATT2_SMEM ((2*TOK*ATT_PAD + 16*ATT_PAD) * 4 + 16*200*4)

__global__ __launch_bounds__(256) void attn2(
    const __half* __restrict__ Q, const __half* __restrict__ K,
    const __half* __restrict__ V, __half* __restrict__ a16)
{
    extern __shared__ char smraw[];
    __half2* ks2 = (__half2*)smraw;
    __half2* vs2 = ks2 + TOK * ATT_PAD;
    __half2* qs2 = vs2 + TOK * ATT_PAD;
    float*   sc  = (float*)(qs2 + 16 * ATT_PAD);

    int bh = blockIdx.x;
    int b = bh / HEADS, h = bh % HEADS;
    int tid = threadIdx.x, lane = tid & 31, w = tid >> 5;
    const __half2* Qb = (const __half2*)(Q + (size_t)bh * TOK * DHD);
    const __half2* Kb = (const __half2*)(K + (size_t)bh * TOK * DHD);
    const __half2* Vb = (const __half2*)(V + (size_t)bh * TOK * DHD);

    for (int i = tid; i < TOK * 32; i += 256) {
        int n = i >> 5, d2 = i & 31;
        ks2[n * ATT_PAD + d2] = Kb[i];
        vs2[n * ATT_PAD + d2] = Vb[i];
    }
    __syncthreads();

    float* scw0 = sc + w * 400;
    float* scw1 = scw0 + 200;
    __half2* q0 = qs2 + (w * 2) * ATT_PAD;
    __half2* q1 = q0 + ATT_PAD;

    for (int base = 0; base < TOK; base += 16) {
        int nq0 = base + w * 2, nq1 = nq0 + 1;
        bool ok0 = (nq0 < TOK), ok1 = (nq1 < TOK);
        if (ok0) q0[lane] = Qb[(size_t)nq0 * 32 + lane];
        if (ok1) q1[lane] = Qb[(size_t)nq1 * 32 + lane];
        __syncwarp();
        if (!ok0) { continue; }
        float mx0 = -1e30f, mx1 = -1e30f;
        for (int kk = lane; kk < TOK; kk += 32) {
            float s0 = 0.f, s1 = 0.f;
#pragma unroll
            for (int d2 = 0; d2 < 32; d2++) {
                float2 kv  = __half22float2(ks2[kk * ATT_PAD + d2]);
                float2 qv0 = __half22float2(q0[d2]);
                float2 qv1 = __half22float2(q1[d2]);
                s0 += kv.x * qv0.x + kv.y * qv0.y;
                s1 += kv.x * qv1.x + kv.y * qv1.y;
            }
            scw0[kk] = s0 * 0.125f;
            scw1[kk] = s1 * 0.125f;
            mx0 = fmaxf(mx0, s0 * 0.125f);
            mx1 = fmaxf(mx1, s1 * 0.125f);
        }
#pragma unroll
        for (int o = 16; o > 0; o >>= 1) {
            mx0 = fmaxf(mx0, __shfl_xor_sync(0xffffffffu, mx0, o));
            mx1 = fmaxf(mx1, __shfl_xor_sync(0xffffffffu, mx1, o));
        }
        float sum0 = 0.f, sum1 = 0.f;
        for (int kk = lane; kk < TOK; kk += 32) {
            float p0 = expf(scw0[kk] - mx0);
            float p1 = expf(scw1[kk] - mx1);
            scw0[kk] = p0; scw1[kk] = p1;
            sum0 += p0; sum1 += p1;
        }
        sum0 = wred_sum(sum0); sum1 = wred_sum(sum1);
        float inv0 = 1.f / sum0, inv1 = 1.f / sum1;
        __syncwarp();
        float ax0 = 0.f, ay0 = 0.f, ax1 = 0.f, ay1 = 0.f;
        for (int kk = 0; kk < TOK; kk++) {
            float2 vv = __half22float2(vs2[kk * ATT_PAD + lane]);
            float p0 = scw0[kk], p1 = scw1[kk];
            ax0 += p0 * vv.x; ay0 += p0 * vv.y;
            ax1 += p1 * vv.x; ay1 += p1 * vv.y;
        }
        ax0 *= inv0; ay0 *= inv0; ax1 *= inv1; ay1 *= inv1;
        {
            size_t o0 = ((size_t)(b * TOK + nq0)) * KP2_D + h * DHD + lane * 2;
            __half h0 = __float2half(ax0), h1 = __float2half(ay0);
            a16[o0] = h0; a16[o0 + 1] = h1;
            a16[o0 + DIM]     = __float2half(ax0 - __half2float(h0));
            a16[o0 + DIM + 1] = __float2half(ay0 - __half2float(h1));
        }
        if (ok1) {
            size_t o1 = ((size_t)(b * TOK + nq1)) * KP2_D + h * DHD + lane * 2;
            __half h0 = __float2half(ax1), h1 = __float2half(ay1);
            a16[o1] = h0; a16[o1 + 1] = h1;
            a16[o1 + DIM]     = __float2half(ax1 - __half2float(h0));
            a16[o1 + DIM + 1] = __float2half(ay1 - __half2float(h1));
        }
        __syncwarp();
    }
}

// fp32 SGEMM for the tiny head (M=32)
__global__ __launch_bounds__(256) void sgemm(
    const float* __restrict__ A, int lda,
    const float* __restrict__ W, const float* __restrict__ bias,
    float* __restrict__ C, int ldc, int M, int N, int K, int act)
{
    __shared__ float As[16][128];
    __shared__ float Bs[16][64];
    int tid = threadIdx.x;
    int tx = tid & 15, ty = tid >> 4;
    int row0 = blockIdx.y * 128;
    int col0 = blockIdx.x * 64;
    float acc[8][4];
#pragma unroll
    for (int i = 0; i < 8; i++)
#pragma unroll
        for (int j = 0; j < 4; j++) acc[i][j] = 0.f;
    for (int k0 = 0; k0 < K; k0 += 16) {
#pragma unroll
        for (int i = 0; i < 2; i++) {
            int idx = tid + i * 256;
            int r = idx >> 2, c = (idx & 3) << 2;
            int gr = row0 + r;
            float4 v = make_float4(0.f, 0.f, 0.f, 0.f);
            if (gr < M) v = *(const float4*)(A + (size_t)gr * lda + k0 + c);
            As[c + 0][r] = v.x; As[c + 1][r] = v.y; As[c + 2][r] = v.z; As[c + 3][r] = v.w;
        }
        {
            int n = tid >> 2, c = (tid & 3) << 2;
            int gn = col0 + n;
            float4 v = make_float4(0.f, 0.f, 0.f, 0.f);
            if (gn < N) v = *(const float4*)(W + (size_t)gn * K + k0 + c);
            Bs[c + 0][n] = v.x; Bs[c + 1][n] = v.y; Bs[c + 2][n] = v.z; Bs[c + 3][n] = v.w;
        }
        __syncthreads();
#pragma unroll
        for (int kk = 0; kk < 16; kk++) {
            float4 a0 = *(const float4*)&As[kk][ty * 8];
            float4 a1 = *(const float4*)&As[kk][ty * 8 + 4];
            float4 bb = *(const float4*)&Bs[kk][tx * 4];
            float av[8] = {a0.x, a0.y, a0.z, a0.w, a1.x, a1.y, a1.z, a1.w};
            float bv[4] = {bb.x, bb.y, bb.z, bb.w};
#pragma unroll
            for (int i = 0; i < 8; i++)
#pragma unroll
                for (int j = 0; j < 4; j++) acc[i][j] += av[i] * bv[j];
        }
        __syncthreads();
    }
#pragma unroll
    for (int i = 0; i < 8; i++) {
        int gr = row0 + ty * 8 + i;
        if (gr >= M) continue;
#pragma unroll
        for (int j = 0; j < 4; j++) {
            int gn = col0 + tx * 4 + j;
            if (gn >= N) continue;
            float v = acc[i][j];
            if (bias) v += bias[gn];
            if (act == 2) v = tanhf(v);
            C[(size_t)gr * ldc + gn] = v;
        }
    }
}

extern "C" void kernel_launch(void* const* d_in, const int* in_sizes, int n_in,
                              void* d_out, int out_size)
{
    const float* img     = (const float*)d_in[0];
    const float* patch_w = (const float*)d_in[1];
    const float* patch_b = (const float*)d_in[2];
    const float* cls_tok = (const float*)d_in[3];
    const float* pos_emb = (const float*)d_in[4];
    const float* ln1_w   = (const float*)d_in[5];
    const float* ln1_b   = (const float*)d_in[6];
    const float* qkv_w   = (const float*)d_in[7];
    const float* qkv_b   = (const float*)d_in[8];
    const float* proj_w  = (const float*)d_in[9];
    const float* proj_b  = (const float*)d_in[10];
    const float* ln2_w   = (const float*)d_in[11];
    const float* ln2_b   = (const float*)d_in[12];
    const float* ff1_w   = (const float*)d_in[13];
    const float* ff1_b   = (const float*)d_in[14];
    const float* ff2_w   = (const float*)d_in[15];
    const float* ff2_b   = (const float*)d_in[16];
    const float* head1_w = (const float*)d_in[17];
    const float* head1_b = (const float*)d_in[18];
    const float* head2_w = (const float*)d_in[19];
    const float* head2_b = (const float*)d_in[20];
    float* out = (float*)d_out;

    float *x, *tok, *hh;
    __half *q, *k, *v, *a16, *f16, *wp, *wq, *wpr, *wf1, *wf2;
    cudaGetSymbolAddress((void**)&x,   g_x);
    cudaGetSymbolAddress((void**)&q,   g_q16);
    cudaGetSymbolAddress((void**)&k,   g_k16);
    cudaGetSymbolAddress((void**)&v,   g_v16);
    cudaGetSymbolAddress((void**)&tok, g_tok);
    cudaGetSymbolAddress((void**)&hh,  g_hh);
    cudaGetSymbolAddress((void**)&a16, g_a16);
    cudaGetSymbolAddress((void**)&f16, g_f16);
    cudaGetSymbolAddress((void**)&wp,  g_wp16);
    cudaGetSymbolAddress((void**)&wq,  g_wqkv16);
    cudaGetSymbolAddress((void**)&wpr, g_wpr16);
    cudaGetSymbolAddress((void**)&wf1, g_wf1_16);
    cudaGetSymbolAddress((void**)&wf2, g_wf2_16);

    cudaFuncSetAttribute(hgemm, cudaFuncAttributeMaxDynamicSharedMemorySize, HG_SMEM);
    cudaFuncSetAttribute(attn2, cudaFuncAttributeMaxDynamicSharedMemorySize, ATT2_SMEM);

    long t4;
    t4 = (long)DIM * DIM / 4;
    convert_w<<<(unsigned)((t4 + 255) / 256), 256>>>((const float4*)patch_w, (__half2*)wp, t4);
    t4 = 12L * QKVD * DIM / 4;
    convert_w<<<(unsigned)((t4 + 255) / 256), 256>>>((const float4*)qkv_w, (__half2*)wq, t4);
    t4 = 12L * DIM * DIM / 4;
    convert_w<<<(unsigned)((t4 + 255) / 256), 256>>>((const float4*)proj_w, (__half2*)wpr, t4);
    t4 = 12L * FFD * DIM / 4;
    convert_w<<<(unsigned)((t4 + 255) / 256), 256>>>((const float4*)ff1_w, (__half2*)wf1, t4);
    t4 = 12L * DIM * FFD / 4;
    convert_w<<<(unsigned)((t4 + 255) / 256), 256>>>((const float4*)ff2_w, (__half2*)wf2, t4);

    {
        int tot = PATCH_ROWS * DIM;
        im2col_split<<<(tot + 255) / 256, 256>>>(img, a16);
        hgemm<<<dim3(6, 49), 256, HG_SMEM>>>(a16, wp, DIM, patch_b, (const float*)0,
                                             tok, (__half*)0, (__half*)0, (__half*)0, (__half*)0,
                                             DIM, PATCH_ROWS, 0);
        int tot2 = ROWS * DIM;
        assemble_kernel<<<(tot2 + 255) / 256, 256>>>(tok, cls_tok, pos_emb, x);
    }

    for (int l = 0; l < 12; l++) {
        ln_split_warp<<<(ROWS + 7) / 8, 256>>>(x, ln1_w + (size_t)l * DIM, ln1_b + (size_t)l * DIM, a16);
        hgemm<<<dim3(18, 50), 256, HG_SMEM>>>(a16, wq + (size_t)l * QKVD * DIM, DIM,
                                              qkv_b + (size_t)l * QKVD, (const float*)0,
                                              (float*)0, (__half*)0, q, k, v,
                                              QKVD, ROWS, 3);
        attn2<<<BATCH * HEADS, 256, ATT2_SMEM>>>(q, k, v, a16);
        hgemm<<<dim3(6, 50), 256, HG_SMEM>>>(a16, wpr + (size_t)l * DIM * DIM, DIM,
                                             proj_b + (size_t)l * DIM, x,
                                             x, (__half*)0, (__half*)0, (__half*)0, (__half*)0,
                                             DIM, ROWS, 1);
        ln_split_warp<<<(ROWS + 7) / 8, 256>>>(x, ln2_w + (size_t)l * DIM, ln2_b + (size_t)l * DIM, a16);
        hgemm<<<dim3(24, 50), 256, HG_SMEM>>>(a16, wf1 + (size_t)l * FFD * DIM, DIM,
                                              ff1_b + (size_t)l * FFD, (const float*)0,
                                              (float*)0, f16, (__half*)0, (__half*)0, (__half*)0,
                                              FFD, ROWS, 2);
        hgemm<<<dim3(6, 50), 256, HG_SMEM>>>(f16, wf2 + (size_t)l * DIM * FFD, FFD,
                                             ff2_b + (size_t)l * DIM, x,
                                             x, (__half*)0, (__half*)0, (__half*)0, (__half*)0,
                                             DIM, ROWS, 1);
    }

    sgemm<<<dim3(48, 1), 256>>>(x, TOK * DIM, head1_w, head1_b, hh, FFD, BATCH, FFD, DIM, 2);
    sgemm<<<dim3(16, 1), 256>>>(hh, FFD, head2_w, head2_b, out, NCLSD, BATCH, NCLSD, FFD, 0);
}